// round 10
// baseline (speedup 1.0000x reference)
#include <cuda_runtime.h>
#include <math.h>
#include <stdint.h>

#define BB 8
#define SS 512
#define DD 1024
#define HH 16
#define DQh 64
#define DI 4096
#define LL 6
#define NTOK (BB*SS)
#define EPSLN 1e-5f

// ---------------- device scratch ----------------
__device__ __align__(16) float g_x  [NTOK*DD];
__device__ __align__(16) float g_h  [NTOK*DD];
__device__ __align__(16) float g_q  [NTOK*DD];
__device__ __align__(16) float g_kv [NTOK*2*DD];
__device__ __align__(16) float g_o  [NTOK*DD];
__device__ __align__(16) float g_ffn[NTOK*DI];
__device__ __align__(16) float g_sc [BB*HH*SS*SS];
__device__ __align__(16) float g_pe [SS*DD];
__device__ __align__(16) float g_vt [BB*HH*DQh*SS];
__device__ __align__(16) float g_wq [DD*DD];
__device__ __align__(16) float g_wkv[2*DD*DD];
__device__ __align__(16) float g_wo [DD*DD];
__device__ __align__(16) float g_w1 [DI*DD];
__device__ __align__(16) float g_w2 [DD*DI];

// ---------------- helpers ----------------
__device__ __forceinline__ float warpSum(float v){
#pragma unroll
    for (int o = 16; o; o >>= 1) v += __shfl_xor_sync(0xffffffffu, v, o);
    return v;
}
__device__ __forceinline__ float warpMax(float v){
#pragma unroll
    for (int o = 16; o; o >>= 1) v = fmaxf(v, __shfl_xor_sync(0xffffffffu, v, o));
    return v;
}
__device__ __forceinline__ float cvt_tf32(float x){
    uint32_t u;
    asm("cvt.rna.tf32.f32 %0, %1;" : "=r"(u) : "f"(x));
    return __uint_as_float(u);
}
__device__ __forceinline__ uint32_t smem_u32(const void* p){
    uint32_t a;
    asm("{ .reg .u64 t; cvta.to.shared.u64 t, %1; cvt.u32.u64 %0, t; }" : "=r"(a) : "l"(p));
    return a;
}
__device__ __forceinline__ void cp16(uint32_t s, const void* g){
    asm volatile("cp.async.cg.shared.global [%0], [%1], 16;" :: "r"(s), "l"(g));
}
__device__ __forceinline__ void cp_commit(){
    asm volatile("cp.async.commit_group;" ::: "memory");
}
__device__ __forceinline__ void cp_wait1(){
    asm volatile("cp.async.wait_group 1;" ::: "memory");
}
__device__ __forceinline__ void cp_wait0(){
    asm volatile("cp.async.wait_group 0;" ::: "memory");
}
__device__ __forceinline__ void mma8(float* c, const uint32_t* a, uint32_t b0, uint32_t b1){
    asm volatile("mma.sync.aligned.m16n8k8.row.col.f32.tf32.tf32.f32 "
        "{%0,%1,%2,%3}, {%4,%5,%6,%7}, {%8,%9}, {%0,%1,%2,%3};"
        : "+f"(c[0]), "+f"(c[1]), "+f"(c[2]), "+f"(c[3])
        : "r"(a[0]), "r"(a[1]), "r"(a[2]), "r"(a[3]), "r"(b0), "r"(b1));
}
// permuted column position within K-group kg
__device__ __forceinline__ int pcol(int n, int kg){
    int blk = n & ~(kg - 1);
    int r   = n & (kg - 1);
    return blk + (r & 3) * (kg >> 2) + (r >> 2);
}

// ---------------- positional encoding ----------------
__global__ void pe_kernel(float* __restrict__ pe){
    int idx = blockIdx.x * 256 + threadIdx.x;
    if (idx >= SS*DD) return;
    int s = idx / DD, d = idx % DD;
    double expo  = (double)(2 * (d / 2)) / (double)DD;
    double denom = pow(10000.0, expo);
    double ang   = (double)s / denom;
    pe[idx] = (float)((d % 2 == 0) ? sin(ang) : cos(ang));
}

__global__ void embed_kernel(const int* __restrict__ tokens,
                             const float* __restrict__ emb,
                             const float* __restrict__ pe,
                             float* __restrict__ x){
    int idx = blockIdx.x * 256 + threadIdx.x;
    int row = idx / DD, d = idx % DD;
    int s = row % SS;
    int t = tokens[row];
    x[idx] = emb[(long long)t * DD + d] * 32.0f + pe[s * DD + d];
}

// ---------------- layernorm (mode=1: tf32-round + perm1024 output) ----------------
__global__ void ln_kernel(const float* __restrict__ x,
                          const float* __restrict__ g,
                          const float* __restrict__ be,
                          float* __restrict__ y, int mode){
    int row = blockIdx.x, tid = threadIdx.x;
    const float4* xr = (const float4*)(x + (long long)row * DD);
    float4 v = xr[tid];
    float s  = v.x + v.y + v.z + v.w;
    float sq = v.x*v.x + v.y*v.y + v.z*v.z + v.w*v.w;
    __shared__ float sh[16];
    s  = warpSum(s);
    sq = warpSum(sq);
    int wid = tid >> 5, lid = tid & 31;
    if (lid == 0){ sh[wid] = s; sh[wid + 8] = sq; }
    __syncthreads();
    if (wid == 0){
        float a  = (lid < 8) ? sh[lid]     : 0.f;
        float b2 = (lid < 8) ? sh[lid + 8] : 0.f;
        a  = warpSum(a);
        b2 = warpSum(b2);
        if (lid == 0){ sh[0] = a; sh[1] = b2; }
    }
    __syncthreads();
    float mean = sh[0] * (1.0f / DD);
    float var  = sh[1] * (1.0f / DD) - mean * mean;
    float rstd = rsqrtf(var + EPSLN);
    float4 gv = ((const float4*)g)[tid];
    float4 bv = ((const float4*)be)[tid];
    float4 o;
    o.x = (v.x - mean) * rstd * gv.x + bv.x;
    o.y = (v.y - mean) * rstd * gv.y + bv.y;
    o.z = (v.z - mean) * rstd * gv.z + bv.z;
    o.w = (v.w - mean) * rstd * gv.w + bv.w;
    if (mode){
        long long rb = (long long)row * DD;
        // d = 4*tid + c  ->  perm1024 = c*256 + tid
        y[rb +   0 + tid] = cvt_tf32(o.x);
        y[rb + 256 + tid] = cvt_tf32(o.y);
        y[rb + 512 + tid] = cvt_tf32(o.z);
        y[rb + 768 + tid] = cvt_tf32(o.w);
    } else {
        ((float4*)(y + (long long)row * DD))[tid] = o;
    }
}

// ---------------- masked softmax (tf32-rounded, perm512 output) ----------------
__global__ void softmax_kernel(float* __restrict__ sc, const int* __restrict__ lengths){
    int z = blockIdx.y;
    int q = blockIdx.x;
    int b = z >> 4;
    int len = lengths[b];
    float* row = sc + (((long long)z << 9) + q) * SS;
    int tid = threadIdx.x;
    __shared__ float tmp[SS];
    __shared__ float sh[16];
    float m = -1e30f;
    for (int k = tid; k < len; k += 256){ float v = row[k]; tmp[k] = v; m = fmaxf(m, v); }
    m = warpMax(m);
    int wid = tid >> 5, lid = tid & 31;
    if (lid == 0) sh[wid] = m;
    __syncthreads();
    if (wid == 0){
        float a = (lid < 8) ? sh[lid] : -1e30f;
        a = warpMax(a);
        if (lid == 0) sh[0] = a;
    }
    __syncthreads();
    m = sh[0];
    float s = 0.f;
    for (int k = tid; k < len; k += 256){ float e = expf(tmp[k] - m); tmp[k] = e; s += e; }
    s = warpSum(s);
    if (lid == 0) sh[wid + 8] = s;
    __syncthreads();
    if (wid == 0){
        float a = (lid < 8) ? sh[lid + 8] : 0.f;
        a = warpSum(a);
        if (lid == 0) sh[1] = a;
    }
    __syncthreads();
    float inv = 1.0f / sh[1];
    for (int k = tid; k < SS; k += 256){
        int kp = ((k & 3) << 7) + (k >> 2);
        row[kp] = (k < len) ? cvt_tf32(tmp[k] * inv) : 0.0f;
    }
}

// ---------------- weight transpose: dst[c][permR(r)] = tf32(src[r][c]) ----------------
__global__ void transpose_kernel(const float* __restrict__ src, float* __restrict__ dst,
                                 int R, int C){
    __shared__ float t[32][33];
    int c0 = blockIdx.x * 32, r0 = blockIdx.y * 32;
    int x = threadIdx.x, y = threadIdx.y;
#pragma unroll
    for (int j = 0; j < 4; j++)
        t[y + j*8][x] = cvt_tf32(src[(long long)(r0 + y + j*8) * C + c0 + x]);
    __syncthreads();
    int R4 = R >> 2;
#pragma unroll
    for (int j = 0; j < 4; j++){
        int r = r0 + x;
        int pr = (r & 3) * R4 + (r >> 2);
        dst[(long long)(c0 + y + j*8) * R + pr] = t[x][y + j*8];
    }
}

// V transpose: read kv (perm64 within head), write vt[z][d][perm512(t)]
__global__ void vtrans_kernel(const float* __restrict__ kv, float* __restrict__ vt){
    __shared__ float t[32][33];
    int z = blockIdx.z;
    int b = z >> 4, h = z & 15;
    int d0 = blockIdx.x * 32, t0 = blockIdx.y * 32;
    const float* src = kv + (long long)b * 512 * 2048 + 1024 + h * 64;
    float* dst = vt + (long long)z * 64 * 512;
    int x = threadIdx.x, y = threadIdx.y;
    int d = d0 + x;
    int dp = ((d & 3) << 4) + (d >> 2);   // perm64
#pragma unroll
    for (int j = 0; j < 4; j++)
        t[y + j*8][x] = src[(long long)(t0 + y + j*8) * 2048 + dp];
    __syncthreads();
    int tt = t0 + x;
    int tp = ((tt & 3) << 7) + (tt >> 2); // perm512
#pragma unroll
    for (int j = 0; j < 4; j++)
        dst[(long long)(d0 + y + j*8) * 512 + tp] = t[x][y + j*8];
}

// ---------------- tf32 mma.sync batched GEMM, crosswise-K layout, 3-stage cp.async ----
// All operands stored K-permuted: pos(k) = (k&3)*(K/4) + (k>>2).
// C[m][n] = alpha*sum_k A[m][k]*B[n][k] (+bias)(relu)(+res)(rnd_out)(perm-out kg)
template<int BN>
__global__ void __launch_bounds__(256, 2)
mma_gemm(int K,
         const float* __restrict__ A, int lda, long long sAb, long long sAh,
         const float* __restrict__ B, int ldb, long long sBb, long long sBh,
         float*       __restrict__ C, int ldc, long long sCb, long long sCh, int colh,
         const float* __restrict__ bias, const float* __restrict__ res,
         float alpha, int relu, int rnd_out, int kg, int batchH)
{
    constexpr int BM  = 128;
    constexpr int RS  = 36;               // smem row stride (floats)
    constexpr int STG = (BM + BN) * RS;   // floats per stage
    constexpr int NF  = BN / 16;
    constexpr int NBI = BN / 32;

    extern __shared__ float smp[];

    const int tid = threadIdx.x;
    const int wid = tid >> 5, lid = tid & 31;
    const int wm = wid >> 1, wn = wid & 1;
    const int tg = lid >> 2, tig = lid & 3;

    int z  = blockIdx.z;
    int bb = z / batchH, hh = z - bb * batchH;
    A += bb * sAb + hh * sAh;
    B += bb * sBb + hh * sBh;
    long long coff = bb * sCb + hh * sCh;
    const int colbase = hh * colh;

    const int m0 = blockIdx.y * BM;
    const int n0 = blockIdx.x * BN;

    const int K4  = K >> 2;
    const int nst = K >> 5;

    // staging: row = tid>>3; slot: c-class = (tid>>1)&3, half = tid&1
    const int srow  = tid >> 3;
    const int c_cls = (tid >> 1) & 3;
    const int half  = tid & 1;
    const float* Ab = A + (long long)(m0 + srow) * lda + c_cls * K4 + half * 4;
    const float* Bb = B + (long long)(n0 + srow) * ldb + c_cls * K4 + half * 4;
    const uint32_t smem0 = smem_u32(smp);
    const uint32_t aoff = (uint32_t)(srow * RS + c_cls * 8 + half * 4) * 4;
    const uint32_t boff = (uint32_t)(BM * RS + srow * RS + c_cls * 8 + half * 4) * 4;

    float acc[2][NF][4];
#pragma unroll
    for (int i = 0; i < 2; i++)
#pragma unroll
        for (int j = 0; j < NF; j++)
#pragma unroll
            for (int q = 0; q < 4; q++) acc[i][j][q] = 0.f;

#define ISSUE(sidx) do{ \
    uint32_t sb = smem0 + (uint32_t)(((sidx) % 3) * STG) * 4; \
    const float* Ag = Ab + (sidx) * 8; \
    const float* Bg = Bb + (sidx) * 8; \
    _Pragma("unroll") \
    for (int i = 0; i < 4; i++) \
        cp16(sb + aoff + (uint32_t)i * 32 * RS * 4, Ag + (long long)i * 32 * lda); \
    _Pragma("unroll") \
    for (int i = 0; i < NBI; i++) \
        cp16(sb + boff + (uint32_t)i * 32 * RS * 4, Bg + (long long)i * 32 * ldb); \
    cp_commit(); \
}while(0)

    ISSUE(0);
    if (nst > 1) ISSUE(1);

    for (int s = 0; s < nst; s++){
        if (s + 1 < nst) cp_wait1(); else cp_wait0();
        __syncthreads();
        if (s + 2 < nst) ISSUE(s + 2);

        const float* As = smp + (s % 3) * STG;
        const float* Bs = As + BM * RS;

        // A fragments: 4 rows x 2 halves as float4
        float4 a4[4][2];
#pragma unroll
        for (int mi = 0; mi < 2; mi++){
            int rb = wm * 32 + mi * 16 + tg;
#pragma unroll
            for (int hf = 0; hf < 2; hf++){
                a4[mi*2+0][hf] = *(const float4*)(As + rb * RS + tig * 8 + hf * 4);
                a4[mi*2+1][hf] = *(const float4*)(As + (rb + 8) * RS + tig * 8 + hf * 4);
            }
        }
#pragma unroll
        for (int ni = 0; ni < NF; ni++){
            int rb = wn * (BN / 2) + ni * 8 + tg;
            float4 b0h = *(const float4*)(Bs + rb * RS + tig * 8);
            float4 b1h = *(const float4*)(Bs + rb * RS + tig * 8 + 4);
#pragma unroll
            for (int j8 = 0; j8 < 4; j8++){
                const float4& bh = (j8 < 2) ? b0h : b1h;
                uint32_t bb0, bb1;
                if ((j8 & 1) == 0){ bb0 = __float_as_uint(bh.x); bb1 = __float_as_uint(bh.y); }
                else              { bb0 = __float_as_uint(bh.z); bb1 = __float_as_uint(bh.w); }
#pragma unroll
                for (int mi = 0; mi < 2; mi++){
                    const float4& a0 = a4[mi*2+0][j8 >> 1];
                    const float4& a1 = a4[mi*2+1][j8 >> 1];
                    uint32_t af[4];
                    if ((j8 & 1) == 0){
                        af[0] = __float_as_uint(a0.x); af[1] = __float_as_uint(a1.x);
                        af[2] = __float_as_uint(a0.y); af[3] = __float_as_uint(a1.y);
                    } else {
                        af[0] = __float_as_uint(a0.z); af[1] = __float_as_uint(a1.z);
                        af[2] = __float_as_uint(a0.w); af[3] = __float_as_uint(a1.w);
                    }
                    mma8(acc[mi][ni], af, bb0, bb1);
                }
            }
        }
    }
#undef ISSUE

    // ---- epilogue ----
    float* Cp = C + coff;
    const float* Rp = res ? res + coff : nullptr;
#pragma unroll
    for (int mi = 0; mi < 2; mi++){
        int r0 = m0 + wm * 32 + mi * 16 + tg;
#pragma unroll
        for (int ni = 0; ni < NF; ni++){
            int cc = n0 + wn * (BN / 2) + ni * 8 + tig * 2;
            int cg = colbase + cc;
            float bx = 0.f, by = 0.f;
            if (bias){ bx = bias[cg]; by = bias[cg + 1]; }
#pragma unroll
            for (int hrow = 0; hrow < 2; hrow++){
                int r = r0 + hrow * 8;
                float v0 = acc[mi][ni][hrow * 2 + 0] * alpha + bx;
                float v1 = acc[mi][ni][hrow * 2 + 1] * alpha + by;
                if (relu){ v0 = fmaxf(v0, 0.f); v1 = fmaxf(v1, 0.f); }
                if (Rp){
                    float2 rv = *(const float2*)(Rp + (long long)r * ldc + cc);
                    v0 += rv.x; v1 += rv.y;
                }
                if (rnd_out){ v0 = cvt_tf32(v0); v1 = cvt_tf32(v1); }
                if (kg){
                    Cp[(long long)r * ldc + pcol(cg,     kg)] = v0;
                    Cp[(long long)r * ldc + pcol(cg + 1, kg)] = v1;
                } else {
                    float2 o; o.x = v0; o.y = v1;
                    *(float2*)(Cp + (long long)r * ldc + cc) = o;
                }
            }
        }
    }
}

// ---------------- host side ----------------
#define SM128 (3 * (128 + 128) * 36 * 4)   // 110592
#define SM64  (3 * (128 + 64)  * 36 * 4)   // 82944

static void big_gemm(const float* A, int lda, const float* Bt, int ldb,
                     float* C, int ldc, const float* bias, const float* res,
                     int M, int N, int K, int relu, int rnd_out, int kg){
    dim3 grid(N / 128, M / 128, 1);
    mma_gemm<128><<<grid, 256, SM128>>>(
        K, A, lda, 0, 0, Bt, ldb, 0, 0, C, ldc, 0, 0, 0,
        bias, res, 1.0f, relu, rnd_out, kg, 1);
}

extern "C" void kernel_launch(void* const* d_in, const int* in_sizes, int n_in,
                              void* d_out, int out_size){
    const int*   tokens    = (const int*)  d_in[0];
    const int*   lengths   = (const int*)  d_in[1];
    const float* emb       = (const float*)d_in[2];
    const float* Wq        = (const float*)d_in[3];
    const float* bq        = (const float*)d_in[4];
    const float* Wkv       = (const float*)d_in[5];
    const float* bkv       = (const float*)d_in[6];
    const float* Wo        = (const float*)d_in[7];
    const float* bo        = (const float*)d_in[8];
    const float* ln_attn_g = (const float*)d_in[9];
    const float* ln_attn_b = (const float*)d_in[10];
    const float* W1        = (const float*)d_in[11];
    const float* b1        = (const float*)d_in[12];
    const float* W2        = (const float*)d_in[13];
    const float* b2        = (const float*)d_in[14];
    const float* ln_ffn_g  = (const float*)d_in[15];
    const float* ln_ffn_b  = (const float*)d_in[16];
    const float* ln_f_g    = (const float*)d_in[17];
    const float* ln_f_b    = (const float*)d_in[18];
    float* out = (float*)d_out;

    cudaFuncSetAttribute((const void*)mma_gemm<128>, cudaFuncAttributeMaxDynamicSharedMemorySize, SM128);
    cudaFuncSetAttribute((const void*)mma_gemm<64>,  cudaFuncAttributeMaxDynamicSharedMemorySize, SM64);

    float *xb, *hb, *qb, *kvb, *ob, *fb, *scb, *peb, *vtb;
    float *wqt, *wkvt, *wot, *w1t, *w2t;
    cudaGetSymbolAddress((void**)&xb,   g_x);
    cudaGetSymbolAddress((void**)&hb,   g_h);
    cudaGetSymbolAddress((void**)&qb,   g_q);
    cudaGetSymbolAddress((void**)&kvb,  g_kv);
    cudaGetSymbolAddress((void**)&ob,   g_o);
    cudaGetSymbolAddress((void**)&fb,   g_ffn);
    cudaGetSymbolAddress((void**)&scb,  g_sc);
    cudaGetSymbolAddress((void**)&peb,  g_pe);
    cudaGetSymbolAddress((void**)&vtb,  g_vt);
    cudaGetSymbolAddress((void**)&wqt,  g_wq);
    cudaGetSymbolAddress((void**)&wkvt, g_wkv);
    cudaGetSymbolAddress((void**)&wot,  g_wo);
    cudaGetSymbolAddress((void**)&w1t,  g_w1);
    cudaGetSymbolAddress((void**)&w2t,  g_w2);

    pe_kernel<<<(SS*DD + 255)/256, 256>>>(peb);
    embed_kernel<<<(NTOK*DD)/256, 256>>>(tokens, emb, peb, xb);

    dim3 tb(32, 8);
    const long long SC_Z = (long long)SS * SS;
    for (int l = 0; l < LL; l++){
        // ---- attention sublayer ----
        ln_kernel<<<NTOK, 256>>>(xb, ln_attn_g + l*DD, ln_attn_b + l*DD, hb, 1);

        transpose_kernel<<<dim3(DD/32,   DD/32), tb>>>(Wq  + (long long)l*DD*DD,   wqt,  DD, DD);
        transpose_kernel<<<dim3(2*DD/32, DD/32), tb>>>(Wkv + (long long)l*DD*2*DD, wkvt, DD, 2*DD);

        big_gemm(hb, DD, wqt,  DD, qb,  DD,   bq  + l*DD,   nullptr, NTOK, DD,   DD, 0, 1, 64);
        big_gemm(hb, DD, wkvt, DD, kvb, 2*DD, bkv + l*2*DD, nullptr, NTOK, 2*DD, DD, 0, 1, 64);

        // scores[z,q,k] = 0.125 * Q_z @ K_z^T
        mma_gemm<128><<<dim3(SS/128, SS/128, BB*HH), 256, SM128>>>(
            64,
            qb,  DD,   (long long)SS*DD,   64,
            kvb, 2*DD, (long long)SS*2*DD, 64,
            scb, SS,   (long long)HH*SC_Z, SC_Z, 0,
            nullptr, nullptr, 0.125f, 0, 0, 0, HH);

        softmax_kernel<<<dim3(SS, BB*HH), 256>>>(scb, lengths);

        // V transpose then o[z] = P_z @ V_z
        vtrans_kernel<<<dim3(2, 16, BB*HH), tb>>>(kvb, vtb);
        mma_gemm<64><<<dim3(1, SS/128, BB*HH), 256, SM64>>>(
            SS,
            scb, SS,  (long long)HH*SC_Z,        SC_Z,
            vtb, SS,  (long long)HH*DQh*SS,      (long long)DQh*SS,
            ob,  DD,  (long long)SS*DD,          0, DQh,
            nullptr, nullptr, 1.0f, 0, 1, 1024, HH);

        // x = x + o @ Wo + bo
        transpose_kernel<<<dim3(DD/32, DD/32), tb>>>(Wo + (long long)l*DD*DD, wot, DD, DD);
        big_gemm(ob, DD, wot, DD, xb, DD, bo + l*DD, xb, NTOK, DD, DD, 0, 0, 0);

        // ---- FFN sublayer ----
        ln_kernel<<<NTOK, 256>>>(xb, ln_ffn_g + l*DD, ln_ffn_b + l*DD, hb, 1);
        transpose_kernel<<<dim3(DI/32, DD/32), tb>>>(W1 + (long long)l*DD*DI, w1t, DD, DI);
        big_gemm(hb, DD, w1t, DD, fb, DI, b1 + l*DI, nullptr, NTOK, DI, DD, 1, 1, 4096);
        transpose_kernel<<<dim3(DD/32, DI/32), tb>>>(W2 + (long long)l*DI*DD, w2t, DI, DD);
        big_gemm(fb, DI, w2t, DI, xb, DD, b2 + l*DD, xb, NTOK, DD, DI, 0, 0, 0);
    }

    ln_kernel<<<NTOK, 256>>>(xb, ln_f_g, ln_f_b, out, 0);
}

// round 11
// speedup vs baseline: 2.2476x; 2.2476x over previous
#include <cuda_runtime.h>
#include <cuda_fp16.h>
#include <math.h>
#include <stdint.h>

#define BB 8
#define SS 512
#define DD 1024
#define HH 16
#define DQh 64
#define DI 4096
#define LL 6
#define NTOK (BB*SS)
#define EPSLN 1e-5f

// ---------------- device scratch ----------------
__device__ __align__(16) float  g_x  [NTOK*DD];
__device__ __align__(16) float  g_sc [BB*HH*SS*SS];
__device__ __align__(16) float  g_pe [SS*DD];
__device__ __align__(16) __half g_h  [NTOK*DD];
__device__ __align__(16) __half g_q  [NTOK*DD];
__device__ __align__(16) __half g_kv [NTOK*2*DD];
__device__ __align__(16) __half g_o  [NTOK*DD];
__device__ __align__(16) __half g_ffn[NTOK*DI];
__device__ __align__(16) __half g_sch[BB*HH*SS*SS];
__device__ __align__(16) __half g_vt [BB*HH*DQh*SS];
__device__ __align__(16) __half g_wq [DD*DD];
__device__ __align__(16) __half g_wkv[2*DD*DD];
__device__ __align__(16) __half g_wo [DD*DD];
__device__ __align__(16) __half g_w1 [DI*DD];
__device__ __align__(16) __half g_w2 [DD*DI];

// ---------------- helpers ----------------
__device__ __forceinline__ float warpSum(float v){
#pragma unroll
    for (int o = 16; o; o >>= 1) v += __shfl_xor_sync(0xffffffffu, v, o);
    return v;
}
__device__ __forceinline__ float warpMax(float v){
#pragma unroll
    for (int o = 16; o; o >>= 1) v = fmaxf(v, __shfl_xor_sync(0xffffffffu, v, o));
    return v;
}
__device__ __forceinline__ uint32_t smem_u32(const void* p){
    uint32_t a;
    asm("{ .reg .u64 t; cvta.to.shared.u64 t, %1; cvt.u32.u64 %0, t; }" : "=r"(a) : "l"(p));
    return a;
}
__device__ __forceinline__ void cp16(uint32_t s, const void* g){
    asm volatile("cp.async.cg.shared.global [%0], [%1], 16;" :: "r"(s), "l"(g));
}
__device__ __forceinline__ void cp_commit(){
    asm volatile("cp.async.commit_group;" ::: "memory");
}
__device__ __forceinline__ void cp_wait1(){
    asm volatile("cp.async.wait_group 1;" ::: "memory");
}
__device__ __forceinline__ void cp_wait0(){
    asm volatile("cp.async.wait_group 0;" ::: "memory");
}
__device__ __forceinline__ void mma16(float* c, uint32_t a0, uint32_t a1, uint32_t a2, uint32_t a3,
                                      uint32_t b0, uint32_t b1){
    asm volatile("mma.sync.aligned.m16n8k16.row.col.f32.f16.f16.f32 "
        "{%0,%1,%2,%3}, {%4,%5,%6,%7}, {%8,%9}, {%0,%1,%2,%3};"
        : "+f"(c[0]), "+f"(c[1]), "+f"(c[2]), "+f"(c[3])
        : "r"(a0), "r"(a1), "r"(a2), "r"(a3), "r"(b0), "r"(b1));
}

// ---------------- positional encoding ----------------
__global__ void pe_kernel(float* __restrict__ pe){
    int idx = blockIdx.x * 256 + threadIdx.x;
    if (idx >= SS*DD) return;
    int s = idx / DD, d = idx % DD;
    double expo  = (double)(2 * (d / 2)) / (double)DD;
    double denom = pow(10000.0, expo);
    double ang   = (double)s / denom;
    pe[idx] = (float)((d % 2 == 0) ? sin(ang) : cos(ang));
}

__global__ void embed_kernel(const int* __restrict__ tokens,
                             const float* __restrict__ emb,
                             const float* __restrict__ pe,
                             float* __restrict__ x){
    int idx = blockIdx.x * 256 + threadIdx.x;
    int row = idx / DD, d = idx % DD;
    int s = row % SS;
    int t = tokens[row];
    x[idx] = emb[(long long)t * DD + d] * 32.0f + pe[s * DD + d];
}

// ---------------- layernorm: fp32 out (yf) or fp16 out (yh) ----------------
__global__ void ln_kernel(const float* __restrict__ x,
                          const float* __restrict__ g,
                          const float* __restrict__ be,
                          float* __restrict__ yf, __half* __restrict__ yh){
    int row = blockIdx.x, tid = threadIdx.x;
    const float4* xr = (const float4*)(x + (long long)row * DD);
    float4 v = xr[tid];
    float s  = v.x + v.y + v.z + v.w;
    float sq = v.x*v.x + v.y*v.y + v.z*v.z + v.w*v.w;
    __shared__ float sh[16];
    s  = warpSum(s);
    sq = warpSum(sq);
    int wid = tid >> 5, lid = tid & 31;
    if (lid == 0){ sh[wid] = s; sh[wid + 8] = sq; }
    __syncthreads();
    if (wid == 0){
        float a  = (lid < 8) ? sh[lid]     : 0.f;
        float b2 = (lid < 8) ? sh[lid + 8] : 0.f;
        a  = warpSum(a);
        b2 = warpSum(b2);
        if (lid == 0){ sh[0] = a; sh[1] = b2; }
    }
    __syncthreads();
    float mean = sh[0] * (1.0f / DD);
    float var  = sh[1] * (1.0f / DD) - mean * mean;
    float rstd = rsqrtf(var + EPSLN);
    float4 gv = ((const float4*)g)[tid];
    float4 bv = ((const float4*)be)[tid];
    float4 o;
    o.x = (v.x - mean) * rstd * gv.x + bv.x;
    o.y = (v.y - mean) * rstd * gv.y + bv.y;
    o.z = (v.z - mean) * rstd * gv.z + bv.z;
    o.w = (v.w - mean) * rstd * gv.w + bv.w;
    if (yh){
        __half2* hp = (__half2*)(yh + (long long)row * DD + 4 * tid);
        hp[0] = __floats2half2_rn(o.x, o.y);
        hp[1] = __floats2half2_rn(o.z, o.w);
    } else {
        ((float4*)(yf + (long long)row * DD))[tid] = o;
    }
}

// ---------------- masked softmax: fp32 scores in, fp16 probs out ----------------
__global__ void softmax_kernel(const float* __restrict__ sc, __half* __restrict__ sch,
                               const int* __restrict__ lengths){
    int z = blockIdx.y;
    int q = blockIdx.x;
    int b = z >> 4;
    int len = lengths[b];
    const float* row = sc  + (((long long)z << 9) + q) * SS;
    __half* rowh     = sch + (((long long)z << 9) + q) * SS;
    int tid = threadIdx.x;
    __shared__ float tmp[SS];
    __shared__ float sh[16];
    float m = -1e30f;
    for (int k = tid; k < len; k += 256){ float v = row[k]; tmp[k] = v; m = fmaxf(m, v); }
    m = warpMax(m);
    int wid = tid >> 5, lid = tid & 31;
    if (lid == 0) sh[wid] = m;
    __syncthreads();
    if (wid == 0){
        float a = (lid < 8) ? sh[lid] : -1e30f;
        a = warpMax(a);
        if (lid == 0) sh[0] = a;
    }
    __syncthreads();
    m = sh[0];
    float s = 0.f;
    for (int k = tid; k < len; k += 256){ float e = expf(tmp[k] - m); tmp[k] = e; s += e; }
    s = warpSum(s);
    if (lid == 0) sh[wid + 8] = s;
    __syncthreads();
    if (wid == 0){
        float a = (lid < 8) ? sh[lid + 8] : 0.f;
        a = warpSum(a);
        if (lid == 0) sh[1] = a;
    }
    __syncthreads();
    float inv = 1.0f / sh[1];
    for (int k = tid; k < SS; k += 256)
        rowh[k] = __float2half((k < len) ? tmp[k] * inv : 0.0f);
}

// ---------------- weight transpose: dst_h[c][r] = half(src[r][c]) ----------------
__global__ void transpose_kernel(const float* __restrict__ src, __half* __restrict__ dst,
                                 int R, int C){
    __shared__ float t[32][33];
    int c0 = blockIdx.x * 32, r0 = blockIdx.y * 32;
    int x = threadIdx.x, y = threadIdx.y;
#pragma unroll
    for (int j = 0; j < 4; j++)
        t[y + j*8][x] = src[(long long)(r0 + y + j*8) * C + c0 + x];
    __syncthreads();
#pragma unroll
    for (int j = 0; j < 4; j++)
        dst[(long long)(c0 + y + j*8) * R + r0 + x] = __float2half(t[x][y + j*8]);
}

// V transpose: vt[z][d][t] = kv_h[b*512+t][1024 + h*64 + d]
__global__ void vtrans_kernel(const __half* __restrict__ kv, __half* __restrict__ vt){
    __shared__ __half t[32][34];
    int z = blockIdx.z;
    int b = z >> 4, h = z & 15;
    int d0 = blockIdx.x * 32, t0 = blockIdx.y * 32;
    const __half* src = kv + (long long)b * 512 * 2048 + 1024 + h * 64;
    __half* dst = vt + (long long)z * 64 * 512;
    int x = threadIdx.x, y = threadIdx.y;
#pragma unroll
    for (int j = 0; j < 4; j++)
        t[y + j*8][x] = src[(long long)(t0 + y + j*8) * 2048 + d0 + x];
    __syncthreads();
#pragma unroll
    for (int j = 0; j < 4; j++)
        dst[(long long)(d0 + y + j*8) * 512 + t0 + x] = t[x][y + j*8];
}

// ---------------- fp16 mma.sync batched GEMM, 3-stage cp.async ----------------
// C[m][n] = alpha * sum_k A[m][k]*B[n][k] (+bias)(relu)(+res)
// A: [M][K] halves (lda), B: [N][K] halves (ldb). Output: Cf fp32 or Ch fp16.
template<int BN>
__global__ void __launch_bounds__(256, 2)
hgemm(int K,
      const __half* __restrict__ A, int lda, long long sAb, long long sAh,
      const __half* __restrict__ B, int ldb, long long sBb, long long sBh,
      float* __restrict__ Cf, __half* __restrict__ Ch,
      int ldc, long long sCb, long long sCh,
      const float* __restrict__ bias, const float* __restrict__ res,
      float alpha, int relu, int batchH)
{
    constexpr int BM  = 128;
    constexpr int RSh = 40;                 // smem row stride in halves (80B, 16B-aligned)
    constexpr int STG = (BM + BN) * RSh;    // halves per stage
    constexpr int NF  = BN / 16;
    constexpr int NBI = (BN * 4) / 256;     // B staging iters

    extern __shared__ __half smp[];

    const int tid = threadIdx.x;
    const int wid = tid >> 5, lid = tid & 31;
    const int wm = wid >> 1, wn = wid & 1;
    const int tg = lid >> 2, tig = lid & 3;

    int z  = blockIdx.z;
    int bb = z / batchH, hh = z - bb * batchH;
    A += bb * sAb + hh * sAh;
    B += bb * sBb + hh * sBh;
    long long coff = bb * sCb + hh * sCh;

    const int m0 = blockIdx.y * BM;
    const int n0 = blockIdx.x * BN;
    const int nst = K >> 5;                 // 32-k tiles

    // staging: 4 threads per row, 16B (8 halves) each
    const int srow  = tid >> 2;
    const int chnk  = tid & 3;
    const __half* Ab = A + (long long)(m0 + srow) * lda + chnk * 8;
    const __half* Bb = B + (long long)(n0 + srow) * ldb + chnk * 8;
    const uint32_t smem0 = smem_u32(smp);
    const uint32_t aoff = (uint32_t)(srow * RSh + chnk * 8) * 2;
    const uint32_t boff = (uint32_t)(BM * RSh + srow * RSh + chnk * 8) * 2;

    float acc[2][NF][4];
#pragma unroll
    for (int i = 0; i < 2; i++)
#pragma unroll
        for (int j = 0; j < NF; j++)
#pragma unroll
            for (int q = 0; q < 4; q++) acc[i][j][q] = 0.f;

#define ISSUE(sidx) do{ \
    uint32_t sb = smem0 + (uint32_t)(((sidx) % 3) * STG) * 2; \
    const __half* Ag = Ab + (sidx) * 32; \
    const __half* Bg = Bb + (sidx) * 32; \
    _Pragma("unroll") \
    for (int i = 0; i < 2; i++) \
        cp16(sb + aoff + (uint32_t)(i * 64 * RSh) * 2, Ag + (long long)i * 64 * lda); \
    _Pragma("unroll") \
    for (int i = 0; i < NBI; i++) \
        cp16(sb + boff + (uint32_t)(i * 64 * RSh) * 2, Bg + (long long)i * 64 * ldb); \
    cp_commit(); \
}while(0)

    ISSUE(0);
    if (nst > 1) ISSUE(1);

    for (int s = 0; s < nst; s++){
        if (s + 1 < nst) cp_wait1(); else cp_wait0();
        __syncthreads();
        if (s + 2 < nst) ISSUE(s + 2);

        const __half* As = smp + (s % 3) * STG;
        const __half* Bs = As + BM * RSh;

#pragma unroll
        for (int k16 = 0; k16 < 2; k16++){
            const int lo = k16 * 16 + 2 * tig;   // half index of k pair
            uint32_t af[2][4];
#pragma unroll
            for (int mi = 0; mi < 2; mi++){
                int rb = wm * 32 + mi * 16 + tg;
                const __half* ap = As + rb * RSh + lo;
                af[mi][0] = *(const uint32_t*)(ap);
                af[mi][1] = *(const uint32_t*)(ap + 8 * RSh);
                af[mi][2] = *(const uint32_t*)(ap + 8);
                af[mi][3] = *(const uint32_t*)(ap + 8 * RSh + 8);
            }
#pragma unroll
            for (int ni = 0; ni < NF; ni++){
                int rb = wn * (BN / 2) + ni * 8 + tg;
                const __half* bp = Bs + rb * RSh + lo;
                uint32_t b0 = *(const uint32_t*)(bp);
                uint32_t b1 = *(const uint32_t*)(bp + 8);
#pragma unroll
                for (int mi = 0; mi < 2; mi++)
                    mma16(acc[mi][ni], af[mi][0], af[mi][1], af[mi][2], af[mi][3], b0, b1);
            }
        }
        __syncthreads();
    }
#undef ISSUE

    // ---- epilogue ----
    const float* Rp = res ? res + coff : nullptr;
#pragma unroll
    for (int mi = 0; mi < 2; mi++){
        int r0 = m0 + wm * 32 + mi * 16 + tg;
#pragma unroll
        for (int ni = 0; ni < NF; ni++){
            int cc = n0 + wn * (BN / 2) + ni * 8 + tig * 2;
            float bx = 0.f, by = 0.f;
            if (bias){ bx = bias[cc]; by = bias[cc + 1]; }
#pragma unroll
            for (int hrow = 0; hrow < 2; hrow++){
                int r = r0 + hrow * 8;
                float v0 = acc[mi][ni][hrow * 2 + 0] * alpha + bx;
                float v1 = acc[mi][ni][hrow * 2 + 1] * alpha + by;
                if (relu){ v0 = fmaxf(v0, 0.f); v1 = fmaxf(v1, 0.f); }
                long long g = (long long)r * ldc + cc;
                if (Rp){
                    float2 rv = *(const float2*)(Rp + g);
                    v0 += rv.x; v1 += rv.y;
                }
                if (Ch){
                    *(__half2*)(Ch + coff + g) = __floats2half2_rn(v0, v1);
                } else {
                    float2 o; o.x = v0; o.y = v1;
                    *(float2*)(Cf + coff + g) = o;
                }
            }
        }
    }
}

// ---------------- host side ----------------
#define SMH128 (3 * (128 + 128) * 40 * 2)   // 61440
#define SMH64  (3 * (128 + 64)  * 40 * 2)   // 46080

static void big_gemm(const __half* A, int lda, const __half* Bt, int ldb,
                     float* Cf, __half* Ch, int ldc,
                     const float* bias, const float* res,
                     int M, int N, int K, int relu){
    dim3 grid(N / 128, M / 128, 1);
    hgemm<128><<<grid, 256, SMH128>>>(
        K, A, lda, 0, 0, Bt, ldb, 0, 0, Cf, Ch, ldc, 0, 0,
        bias, res, 1.0f, relu, 1);
}

extern "C" void kernel_launch(void* const* d_in, const int* in_sizes, int n_in,
                              void* d_out, int out_size){
    const int*   tokens    = (const int*)  d_in[0];
    const int*   lengths   = (const int*)  d_in[1];
    const float* emb       = (const float*)d_in[2];
    const float* Wq        = (const float*)d_in[3];
    const float* bq        = (const float*)d_in[4];
    const float* Wkv       = (const float*)d_in[5];
    const float* bkv       = (const float*)d_in[6];
    const float* Wo        = (const float*)d_in[7];
    const float* bo        = (const float*)d_in[8];
    const float* ln_attn_g = (const float*)d_in[9];
    const float* ln_attn_b = (const float*)d_in[10];
    const float* W1        = (const float*)d_in[11];
    const float* b1        = (const float*)d_in[12];
    const float* W2        = (const float*)d_in[13];
    const float* b2        = (const float*)d_in[14];
    const float* ln_ffn_g  = (const float*)d_in[15];
    const float* ln_ffn_b  = (const float*)d_in[16];
    const float* ln_f_g    = (const float*)d_in[17];
    const float* ln_f_b    = (const float*)d_in[18];
    float* out = (float*)d_out;

    cudaFuncSetAttribute((const void*)hgemm<128>, cudaFuncAttributeMaxDynamicSharedMemorySize, SMH128);
    cudaFuncSetAttribute((const void*)hgemm<64>,  cudaFuncAttributeMaxDynamicSharedMemorySize, SMH64);

    float *xb, *scb, *peb;
    __half *hb, *qb, *kvb, *ob, *fb, *schb, *vtb;
    __half *wqt, *wkvt, *wot, *w1t, *w2t;
    cudaGetSymbolAddress((void**)&xb,   g_x);
    cudaGetSymbolAddress((void**)&scb,  g_sc);
    cudaGetSymbolAddress((void**)&peb,  g_pe);
    cudaGetSymbolAddress((void**)&hb,   g_h);
    cudaGetSymbolAddress((void**)&qb,   g_q);
    cudaGetSymbolAddress((void**)&kvb,  g_kv);
    cudaGetSymbolAddress((void**)&ob,   g_o);
    cudaGetSymbolAddress((void**)&fb,   g_ffn);
    cudaGetSymbolAddress((void**)&schb, g_sch);
    cudaGetSymbolAddress((void**)&vtb,  g_vt);
    cudaGetSymbolAddress((void**)&wqt,  g_wq);
    cudaGetSymbolAddress((void**)&wkvt, g_wkv);
    cudaGetSymbolAddress((void**)&wot,  g_wo);
    cudaGetSymbolAddress((void**)&w1t,  g_w1);
    cudaGetSymbolAddress((void**)&w2t,  g_w2);

    pe_kernel<<<(SS*DD + 255)/256, 256>>>(peb);
    embed_kernel<<<(NTOK*DD)/256, 256>>>(tokens, emb, peb, xb);

    dim3 tb(32, 8);
    const long long SC_Z = (long long)SS * SS;
    for (int l = 0; l < LL; l++){
        // ---- attention sublayer ----
        ln_kernel<<<NTOK, 256>>>(xb, ln_attn_g + l*DD, ln_attn_b + l*DD, nullptr, hb);

        transpose_kernel<<<dim3(DD/32,   DD/32), tb>>>(Wq  + (long long)l*DD*DD,   wqt,  DD, DD);
        transpose_kernel<<<dim3(2*DD/32, DD/32), tb>>>(Wkv + (long long)l*DD*2*DD, wkvt, DD, 2*DD);

        big_gemm(hb, DD, wqt,  DD, nullptr, qb,  DD,   bq  + l*DD,   nullptr, NTOK, DD,   DD, 0);
        big_gemm(hb, DD, wkvt, DD, nullptr, kvb, 2*DD, bkv + l*2*DD, nullptr, NTOK, 2*DD, DD, 0);

        // scores[z,q,k] = 0.125 * Q_z @ K_z^T  (fp32 out)
        hgemm<128><<<dim3(SS/128, SS/128, BB*HH), 256, SMH128>>>(
            64,
            qb,  DD,   (long long)SS*DD,   64,
            kvb, 2*DD, (long long)SS*2*DD, 64,
            scb, nullptr, SS, (long long)HH*SC_Z, SC_Z,
            nullptr, nullptr, 0.125f, 0, HH);

        softmax_kernel<<<dim3(SS, BB*HH), 256>>>(scb, schb, lengths);

        // V transpose then o[z] = P_z @ V_z  (fp16 out)
        vtrans_kernel<<<dim3(2, 16, BB*HH), tb>>>(kvb, vtb);
        hgemm<64><<<dim3(1, SS/128, BB*HH), 256, SMH64>>>(
            SS,
            schb, SS, (long long)HH*SC_Z,   SC_Z,
            vtb,  SS, (long long)HH*DQh*SS, (long long)DQh*SS,
            nullptr, ob, DD, (long long)SS*DD, DQh,
            nullptr, nullptr, 1.0f, 0, HH);

        // x = x + o @ Wo + bo  (fp32 out + residual)
        transpose_kernel<<<dim3(DD/32, DD/32), tb>>>(Wo + (long long)l*DD*DD, wot, DD, DD);
        big_gemm(ob, DD, wot, DD, xb, nullptr, DD, bo + l*DD, xb, NTOK, DD, DD, 0);

        // ---- FFN sublayer ----
        ln_kernel<<<NTOK, 256>>>(xb, ln_ffn_g + l*DD, ln_ffn_b + l*DD, nullptr, hb);
        transpose_kernel<<<dim3(DI/32, DD/32), tb>>>(W1 + (long long)l*DD*DI, w1t, DD, DI);
        big_gemm(hb, DD, w1t, DD, nullptr, fb, DI, b1 + l*DI, nullptr, NTOK, DI, DD, 1);
        transpose_kernel<<<dim3(DD/32, DI/32), tb>>>(W2 + (long long)l*DI*DD, w2t, DI, DD);
        big_gemm(fb, DI, w2t, DI, xb, nullptr, DD, b2 + l*DD, xb, NTOK, DD, DI, 0);
    }

    ln_kernel<<<NTOK, 256>>>(xb, ln_f_g, ln_f_b, out, nullptr);
}

// round 12
// speedup vs baseline: 2.4422x; 1.0866x over previous
#include <cuda_runtime.h>
#include <cuda_fp16.h>
#include <math.h>
#include <stdint.h>

#define BB 8
#define SS 512
#define DD 1024
#define HH 16
#define DQh 64
#define DI 4096
#define LL 6
#define NTOK (BB*SS)
#define EPSLN 1e-5f

// ---------------- device scratch ----------------
__device__ __align__(16) float  g_x  [NTOK*DD];
__device__ __align__(16) float  g_sc [BB*HH*SS*SS];
__device__ __align__(16) float  g_pe [SS*DD];
__device__ __align__(16) __half g_h  [NTOK*DD];
__device__ __align__(16) __half g_q  [NTOK*DD];
__device__ __align__(16) __half g_kv [NTOK*2*DD];
__device__ __align__(16) __half g_o  [NTOK*DD];
__device__ __align__(16) __half g_ffn[NTOK*DI];
__device__ __align__(16) __half g_sch[BB*HH*SS*SS];
__device__ __align__(16) __half g_vt [BB*HH*DQh*SS];
__device__ __align__(16) __half g_wq [DD*DD];
__device__ __align__(16) __half g_wkv[2*DD*DD];
__device__ __align__(16) __half g_wo [DD*DD];
__device__ __align__(16) __half g_w1 [DI*DD];
__device__ __align__(16) __half g_w2 [DD*DI];

// ---------------- helpers ----------------
__device__ __forceinline__ float warpSum(float v){
#pragma unroll
    for (int o = 16; o; o >>= 1) v += __shfl_xor_sync(0xffffffffu, v, o);
    return v;
}
__device__ __forceinline__ float warpMax(float v){
#pragma unroll
    for (int o = 16; o; o >>= 1) v = fmaxf(v, __shfl_xor_sync(0xffffffffu, v, o));
    return v;
}
__device__ __forceinline__ uint32_t smem_u32(const void* p){
    uint32_t a;
    asm("{ .reg .u64 t; cvta.to.shared.u64 t, %1; cvt.u32.u64 %0, t; }" : "=r"(a) : "l"(p));
    return a;
}
__device__ __forceinline__ void cp16(uint32_t s, const void* g){
    asm volatile("cp.async.cg.shared.global [%0], [%1], 16;" :: "r"(s), "l"(g));
}
__device__ __forceinline__ void cp_commit(){
    asm volatile("cp.async.commit_group;" ::: "memory");
}
__device__ __forceinline__ void cp_wait1(){
    asm volatile("cp.async.wait_group 1;" ::: "memory");
}
__device__ __forceinline__ void cp_wait0(){
    asm volatile("cp.async.wait_group 0;" ::: "memory");
}
__device__ __forceinline__ void mma16(float* c, uint32_t a0, uint32_t a1, uint32_t a2, uint32_t a3,
                                      uint32_t b0, uint32_t b1){
    asm volatile("mma.sync.aligned.m16n8k16.row.col.f32.f16.f16.f32 "
        "{%0,%1,%2,%3}, {%4,%5,%6,%7}, {%8,%9}, {%0,%1,%2,%3};"
        : "+f"(c[0]), "+f"(c[1]), "+f"(c[2]), "+f"(c[3])
        : "r"(a0), "r"(a1), "r"(a2), "r"(a3), "r"(b0), "r"(b1));
}
__device__ __forceinline__ void ldsm4(uint32_t& r0, uint32_t& r1, uint32_t& r2, uint32_t& r3, uint32_t a){
    asm volatile("ldmatrix.sync.aligned.m8n8.x4.shared.b16 {%0,%1,%2,%3}, [%4];"
        : "=r"(r0), "=r"(r1), "=r"(r2), "=r"(r3) : "r"(a));
}

// ---------------- positional encoding ----------------
__global__ void pe_kernel(float* __restrict__ pe){
    int idx = blockIdx.x * 256 + threadIdx.x;
    if (idx >= SS*DD) return;
    int s = idx / DD, d = idx % DD;
    double expo  = (double)(2 * (d / 2)) / (double)DD;
    double denom = pow(10000.0, expo);
    double ang   = (double)s / denom;
    pe[idx] = (float)((d % 2 == 0) ? sin(ang) : cos(ang));
}

__global__ void embed_kernel(const int* __restrict__ tokens,
                             const float* __restrict__ emb,
                             const float* __restrict__ pe,
                             float* __restrict__ x){
    int idx = blockIdx.x * 256 + threadIdx.x;
    int row = idx / DD, d = idx % DD;
    int s = row % SS;
    int t = tokens[row];
    x[idx] = emb[(long long)t * DD + d] * 32.0f + pe[s * DD + d];
}

// ---------------- layernorm: fp32 out (yf) or fp16 out (yh) ----------------
__global__ void ln_kernel(const float* __restrict__ x,
                          const float* __restrict__ g,
                          const float* __restrict__ be,
                          float* __restrict__ yf, __half* __restrict__ yh){
    int row = blockIdx.x, tid = threadIdx.x;
    const float4* xr = (const float4*)(x + (long long)row * DD);
    float4 v = xr[tid];
    float s  = v.x + v.y + v.z + v.w;
    float sq = v.x*v.x + v.y*v.y + v.z*v.z + v.w*v.w;
    __shared__ float sh[16];
    s  = warpSum(s);
    sq = warpSum(sq);
    int wid = tid >> 5, lid = tid & 31;
    if (lid == 0){ sh[wid] = s; sh[wid + 8] = sq; }
    __syncthreads();
    if (wid == 0){
        float a  = (lid < 8) ? sh[lid]     : 0.f;
        float b2 = (lid < 8) ? sh[lid + 8] : 0.f;
        a  = warpSum(a);
        b2 = warpSum(b2);
        if (lid == 0){ sh[0] = a; sh[1] = b2; }
    }
    __syncthreads();
    float mean = sh[0] * (1.0f / DD);
    float var  = sh[1] * (1.0f / DD) - mean * mean;
    float rstd = rsqrtf(var + EPSLN);
    float4 gv = ((const float4*)g)[tid];
    float4 bv = ((const float4*)be)[tid];
    float4 o;
    o.x = (v.x - mean) * rstd * gv.x + bv.x;
    o.y = (v.y - mean) * rstd * gv.y + bv.y;
    o.z = (v.z - mean) * rstd * gv.z + bv.z;
    o.w = (v.w - mean) * rstd * gv.w + bv.w;
    if (yh){
        __half2* hp = (__half2*)(yh + (long long)row * DD + 4 * tid);
        hp[0] = __floats2half2_rn(o.x, o.y);
        hp[1] = __floats2half2_rn(o.z, o.w);
    } else {
        ((float4*)(yf + (long long)row * DD))[tid] = o;
    }
}

// ---------------- masked softmax: fp32 scores in, fp16 probs out ----------------
__global__ void softmax_kernel(const float* __restrict__ sc, __half* __restrict__ sch,
                               const int* __restrict__ lengths){
    int z = blockIdx.y;
    int q = blockIdx.x;
    int b = z >> 4;
    int len = lengths[b];
    const float* row = sc  + (((long long)z << 9) + q) * SS;
    __half* rowh     = sch + (((long long)z << 9) + q) * SS;
    int tid = threadIdx.x;
    __shared__ float tmp[SS];
    __shared__ float sh[16];
    float m = -1e30f;
    for (int k = tid; k < len; k += 256){ float v = row[k]; tmp[k] = v; m = fmaxf(m, v); }
    m = warpMax(m);
    int wid = tid >> 5, lid = tid & 31;
    if (lid == 0) sh[wid] = m;
    __syncthreads();
    if (wid == 0){
        float a = (lid < 8) ? sh[lid] : -1e30f;
        a = warpMax(a);
        if (lid == 0) sh[0] = a;
    }
    __syncthreads();
    m = sh[0];
    float s = 0.f;
    for (int k = tid; k < len; k += 256){ float e = expf(tmp[k] - m); tmp[k] = e; s += e; }
    s = warpSum(s);
    if (lid == 0) sh[wid + 8] = s;
    __syncthreads();
    if (wid == 0){
        float a = (lid < 8) ? sh[lid + 8] : 0.f;
        a = warpSum(a);
        if (lid == 0) sh[1] = a;
    }
    __syncthreads();
    float inv = 1.0f / sh[1];
    for (int k = tid; k < SS; k += 256)
        rowh[k] = __float2half((k < len) ? tmp[k] * inv : 0.0f);
}

// ---------------- weight transpose: dst_h[c][r] = half(src[r][c]) ----------------
__global__ void transpose_kernel(const float* __restrict__ src, __half* __restrict__ dst,
                                 int R, int C){
    __shared__ float t[32][33];
    int c0 = blockIdx.x * 32, r0 = blockIdx.y * 32;
    int x = threadIdx.x, y = threadIdx.y;
#pragma unroll
    for (int j = 0; j < 4; j++)
        t[y + j*8][x] = src[(long long)(r0 + y + j*8) * C + c0 + x];
    __syncthreads();
#pragma unroll
    for (int j = 0; j < 4; j++)
        dst[(long long)(c0 + y + j*8) * R + r0 + x] = __float2half(t[x][y + j*8]);
}

// V transpose: vt[z][d][t] = kv_h[b*512+t][1024 + h*64 + d]
__global__ void vtrans_kernel(const __half* __restrict__ kv, __half* __restrict__ vt){
    __shared__ __half t[32][34];
    int z = blockIdx.z;
    int b = z >> 4, h = z & 15;
    int d0 = blockIdx.x * 32, t0 = blockIdx.y * 32;
    const __half* src = kv + (long long)b * 512 * 2048 + 1024 + h * 64;
    __half* dst = vt + (long long)z * 64 * 512;
    int x = threadIdx.x, y = threadIdx.y;
#pragma unroll
    for (int j = 0; j < 4; j++)
        t[y + j*8][x] = src[(long long)(t0 + y + j*8) * 2048 + d0 + x];
    __syncthreads();
#pragma unroll
    for (int j = 0; j < 4; j++)
        dst[(long long)(d0 + y + j*8) * 512 + t0 + x] = t[x][y + j*8];
}

// ---------------- fp16 mma.sync batched GEMM, ldmatrix + 3-stage cp.async ----------
// C[m][n] = alpha * sum_k A[m][k]*B[n][k] (+bias)(relu)(+res)
template<int BN>
__global__ void __launch_bounds__(256, 2)
hgemm(int K,
      const __half* __restrict__ A, int lda, long long sAb, long long sAh,
      const __half* __restrict__ B, int ldb, long long sBb, long long sBh,
      float* __restrict__ Cf, __half* __restrict__ Ch,
      int ldc, long long sCb, long long sCh,
      const float* __restrict__ bias, const float* __restrict__ res,
      float alpha, int relu, int batchH)
{
    constexpr int BM  = 128;
    constexpr int RSh = 40;                 // smem row stride in halves (80B)
    constexpr int STG = (BM + BN) * RSh;
    constexpr int NF  = BN / 16;
    constexpr int NBI = (BN * 4) / 256;

    extern __shared__ __half smp[];

    const int tid = threadIdx.x;
    const int wid = tid >> 5, lid = tid & 31;
    const int wm = wid >> 1, wn = wid & 1;
    const int tg = lid >> 2, tig = lid & 3;

    int z  = blockIdx.z;
    int bb = z / batchH, hh = z - bb * batchH;
    A += bb * sAb + hh * sAh;
    B += bb * sBb + hh * sBh;
    long long coff = bb * sCb + hh * sCh;

    const int m0 = blockIdx.y * BM;
    const int n0 = blockIdx.x * BN;
    const int nst = K >> 5;

    // staging
    const int srow  = tid >> 2;
    const int chnk  = tid & 3;
    const __half* Ab = A + (long long)(m0 + srow) * lda + chnk * 8;
    const __half* Bb = B + (long long)(n0 + srow) * ldb + chnk * 8;
    const uint32_t smem0 = smem_u32(smp);
    const uint32_t aoff = (uint32_t)(srow * RSh + chnk * 8) * 2;
    const uint32_t boff = (uint32_t)(BM * RSh + srow * RSh + chnk * 8) * 2;

    // ldmatrix per-thread row addressing
    const int lid7 = lid & 7;
    // A x4: mat0=a0(row+0,k+0) mat1=a1(row+8,k+0) mat2=a2(row+0,k+8) mat3=a3(row+8,k+8)
    const uint32_t a_row = wm * 32 + ((lid >> 3) & 1) * 8 + lid7;
    const uint32_t a_kof = (lid >> 4) * 8;
    const uint32_t a_base = (uint32_t)(a_row * RSh + a_kof) * 2;
    // B x4 (n-frag pair): mat0=b0(n+0,k+0) mat1=b1(n+0,k+8) mat2=b0(n+8,k+0) mat3=b1(n+8,k+8->k+8)
    const uint32_t b_row = wn * (BN / 2) + ((lid >> 4) & 1) * 8 + lid7;
    const uint32_t b_kof = ((lid >> 3) & 1) * 8;
    const uint32_t b_base = (uint32_t)((BM + b_row) * RSh + b_kof) * 2;

    float acc[2][NF][4];
#pragma unroll
    for (int i = 0; i < 2; i++)
#pragma unroll
        for (int j = 0; j < NF; j++)
#pragma unroll
            for (int q = 0; q < 4; q++) acc[i][j][q] = 0.f;

#define ISSUE(sidx) do{ \
    uint32_t sb = smem0 + (uint32_t)(((sidx) % 3) * STG) * 2; \
    const __half* Ag = Ab + (sidx) * 32; \
    const __half* Bg = Bb + (sidx) * 32; \
    _Pragma("unroll") \
    for (int i = 0; i < 2; i++) \
        cp16(sb + aoff + (uint32_t)(i * 64 * RSh) * 2, Ag + (long long)i * 64 * lda); \
    _Pragma("unroll") \
    for (int i = 0; i < NBI; i++) \
        cp16(sb + boff + (uint32_t)(i * 64 * RSh) * 2, Bg + (long long)i * 64 * ldb); \
    cp_commit(); \
}while(0)

    ISSUE(0);
    if (nst > 1) ISSUE(1);

    for (int s = 0; s < nst; s++){
        if (s + 1 < nst) cp_wait1(); else cp_wait0();
        __syncthreads();
        if (s + 2 < nst) ISSUE(s + 2);

        const uint32_t stg = smem0 + (uint32_t)((s % 3) * STG) * 2;

#pragma unroll
        for (int k16 = 0; k16 < 2; k16++){
            const uint32_t kby = (uint32_t)(k16 * 16) * 2;
            uint32_t af[2][4];
#pragma unroll
            for (int mi = 0; mi < 2; mi++)
                ldsm4(af[mi][0], af[mi][1], af[mi][2], af[mi][3],
                      stg + a_base + (uint32_t)(mi * 16 * RSh) * 2 + kby);
#pragma unroll
            for (int nip = 0; nip < NF / 2; nip++){
                uint32_t b0, b1, b2, b3;
                ldsm4(b0, b1, b2, b3,
                      stg + b_base + (uint32_t)(nip * 16 * RSh) * 2 + kby);
#pragma unroll
                for (int mi = 0; mi < 2; mi++){
                    mma16(acc[mi][2*nip    ], af[mi][0], af[mi][1], af[mi][2], af[mi][3], b0, b1);
                    mma16(acc[mi][2*nip + 1], af[mi][0], af[mi][1], af[mi][2], af[mi][3], b2, b3);
                }
            }
        }
        __syncthreads();
    }
#undef ISSUE

    // ---- epilogue ----
    const float* Rp = res ? res + coff : nullptr;
#pragma unroll
    for (int mi = 0; mi < 2; mi++){
        int r0 = m0 + wm * 32 + mi * 16 + tg;
#pragma unroll
        for (int ni = 0; ni < NF; ni++){
            int cc = n0 + wn * (BN / 2) + ni * 8 + tig * 2;
            float bx = 0.f, by = 0.f;
            if (bias){ bx = bias[cc]; by = bias[cc + 1]; }
#pragma unroll
            for (int hrow = 0; hrow < 2; hrow++){
                int r = r0 + hrow * 8;
                float v0 = acc[mi][ni][hrow * 2 + 0] * alpha + bx;
                float v1 = acc[mi][ni][hrow * 2 + 1] * alpha + by;
                if (relu){ v0 = fmaxf(v0, 0.f); v1 = fmaxf(v1, 0.f); }
                long long g = (long long)r * ldc + cc;
                if (Rp){
                    float2 rv = *(const float2*)(Rp + g);
                    v0 += rv.x; v1 += rv.y;
                }
                if (Ch){
                    *(__half2*)(Ch + coff + g) = __floats2half2_rn(v0, v1);
                } else {
                    float2 o; o.x = v0; o.y = v1;
                    *(float2*)(Cf + coff + g) = o;
                }
            }
        }
    }
}

// ---------------- host side ----------------
#define SMH128 (3 * (128 + 128) * 40 * 2)
#define SMH64  (3 * (128 + 64)  * 40 * 2)

static void big_gemm(const __half* A, int lda, const __half* Bt, int ldb,
                     float* Cf, __half* Ch, int ldc,
                     const float* bias, const float* res,
                     int M, int N, int K, int relu){
    dim3 grid(N / 128, M / 128, 1);
    hgemm<128><<<grid, 256, SMH128>>>(
        K, A, lda, 0, 0, Bt, ldb, 0, 0, Cf, Ch, ldc, 0, 0,
        bias, res, 1.0f, relu, 1);
}

extern "C" void kernel_launch(void* const* d_in, const int* in_sizes, int n_in,
                              void* d_out, int out_size){
    const int*   tokens    = (const int*)  d_in[0];
    const int*   lengths   = (const int*)  d_in[1];
    const float* emb       = (const float*)d_in[2];
    const float* Wq        = (const float*)d_in[3];
    const float* bq        = (const float*)d_in[4];
    const float* Wkv       = (const float*)d_in[5];
    const float* bkv       = (const float*)d_in[6];
    const float* Wo        = (const float*)d_in[7];
    const float* bo        = (const float*)d_in[8];
    const float* ln_attn_g = (const float*)d_in[9];
    const float* ln_attn_b = (const float*)d_in[10];
    const float* W1        = (const float*)d_in[11];
    const float* b1        = (const float*)d_in[12];
    const float* W2        = (const float*)d_in[13];
    const float* b2        = (const float*)d_in[14];
    const float* ln_ffn_g  = (const float*)d_in[15];
    const float* ln_ffn_b  = (const float*)d_in[16];
    const float* ln_f_g    = (const float*)d_in[17];
    const float* ln_f_b    = (const float*)d_in[18];
    float* out = (float*)d_out;

    cudaFuncSetAttribute((const void*)hgemm<128>, cudaFuncAttributeMaxDynamicSharedMemorySize, SMH128);
    cudaFuncSetAttribute((const void*)hgemm<64>,  cudaFuncAttributeMaxDynamicSharedMemorySize, SMH64);

    float *xb, *scb, *peb;
    __half *hb, *qb, *kvb, *ob, *fb, *schb, *vtb;
    __half *wqt, *wkvt, *wot, *w1t, *w2t;
    cudaGetSymbolAddress((void**)&xb,   g_x);
    cudaGetSymbolAddress((void**)&scb,  g_sc);
    cudaGetSymbolAddress((void**)&peb,  g_pe);
    cudaGetSymbolAddress((void**)&hb,   g_h);
    cudaGetSymbolAddress((void**)&qb,   g_q);
    cudaGetSymbolAddress((void**)&kvb,  g_kv);
    cudaGetSymbolAddress((void**)&ob,   g_o);
    cudaGetSymbolAddress((void**)&fb,   g_ffn);
    cudaGetSymbolAddress((void**)&schb, g_sch);
    cudaGetSymbolAddress((void**)&vtb,  g_vt);
    cudaGetSymbolAddress((void**)&wqt,  g_wq);
    cudaGetSymbolAddress((void**)&wkvt, g_wkv);
    cudaGetSymbolAddress((void**)&wot,  g_wo);
    cudaGetSymbolAddress((void**)&w1t,  g_w1);
    cudaGetSymbolAddress((void**)&w2t,  g_w2);

    pe_kernel<<<(SS*DD + 255)/256, 256>>>(peb);
    embed_kernel<<<(NTOK*DD)/256, 256>>>(tokens, emb, peb, xb);

    dim3 tb(32, 8);
    const long long SC_Z = (long long)SS * SS;
    for (int l = 0; l < LL; l++){
        // ---- attention sublayer ----
        ln_kernel<<<NTOK, 256>>>(xb, ln_attn_g + l*DD, ln_attn_b + l*DD, nullptr, hb);

        transpose_kernel<<<dim3(DD/32,   DD/32), tb>>>(Wq  + (long long)l*DD*DD,   wqt,  DD, DD);
        transpose_kernel<<<dim3(2*DD/32, DD/32), tb>>>(Wkv + (long long)l*DD*2*DD, wkvt, DD, 2*DD);

        big_gemm(hb, DD, wqt,  DD, nullptr, qb,  DD,   bq  + l*DD,   nullptr, NTOK, DD,   DD, 0);
        big_gemm(hb, DD, wkvt, DD, nullptr, kvb, 2*DD, bkv + l*2*DD, nullptr, NTOK, 2*DD, DD, 0);

        // scores[z,q,k] = 0.125 * Q_z @ K_z^T  (fp32 out)
        hgemm<128><<<dim3(SS/128, SS/128, BB*HH), 256, SMH128>>>(
            64,
            qb,  DD,   (long long)SS*DD,   64,
            kvb, 2*DD, (long long)SS*2*DD, 64,
            scb, nullptr, SS, (long long)HH*SC_Z, SC_Z,
            nullptr, nullptr, 0.125f, 0, HH);

        softmax_kernel<<<dim3(SS, BB*HH), 256>>>(scb, schb, lengths);

        // V transpose then o[z] = P_z @ V_z  (fp16 out)
        vtrans_kernel<<<dim3(2, 16, BB*HH), tb>>>(kvb, vtb);
        hgemm<64><<<dim3(1, SS/128, BB*HH), 256, SMH64>>>(
            SS,
            schb, SS, (long long)HH*SC_Z,   SC_Z,
            vtb,  SS, (long long)HH*DQh*SS, (long long)DQh*SS,
            nullptr, ob, DD, (long long)SS*DD, DQh,
            nullptr, nullptr, 1.0f, 0, HH);

        // x = x + o @ Wo + bo  (fp32 out + residual)
        transpose_kernel<<<dim3(DD/32, DD/32), tb>>>(Wo + (long long)l*DD*DD, wot, DD, DD);
        big_gemm(ob, DD, wot, DD, xb, nullptr, DD, bo + l*DD, xb, NTOK, DD, DD, 0);

        // ---- FFN sublayer ----
        ln_kernel<<<NTOK, 256>>>(xb, ln_ffn_g + l*DD, ln_ffn_b + l*DD, nullptr, hb);
        transpose_kernel<<<dim3(DI/32, DD/32), tb>>>(W1 + (long long)l*DD*DI, w1t, DD, DI);
        big_gemm(hb, DD, w1t, DD, nullptr, fb, DI, b1 + l*DI, nullptr, NTOK, DI, DD, 1);
        transpose_kernel<<<dim3(DD/32, DI/32), tb>>>(W2 + (long long)l*DI*DD, w2t, DI, DD);
        big_gemm(fb, DI, w2t, DI, xb, nullptr, DD, b2 + l*DD, xb, NTOK, DD, DI, 0);
    }

    ln_kernel<<<NTOK, 256>>>(xb, ln_f_g, ln_f_b, out, nullptr);
}

// round 13
// speedup vs baseline: 3.1509x; 1.2902x over previous
#include <cuda_runtime.h>
#include <cuda_fp16.h>
#include <math.h>
#include <stdint.h>

#define BB 8
#define SS 512
#define DD 1024
#define HH 16
#define DQh 64
#define DI 4096
#define LL 6
#define NTOK (BB*SS)
#define EPSLN 1e-5f

// ---------------- device scratch ----------------
__device__ __align__(16) float  g_x  [NTOK*DD];
__device__ __align__(16) float  g_pe [SS*DD];
__device__ __align__(16) __half g_h  [NTOK*DD];
__device__ __align__(16) __half g_q  [NTOK*DD];
__device__ __align__(16) __half g_kv [NTOK*2*DD];
__device__ __align__(16) __half g_o  [NTOK*DD];
__device__ __align__(16) __half g_ffn[NTOK*DI];
__device__ __align__(16) __half g_vt [BB*HH*DQh*SS];
__device__ __align__(16) __half g_wq [DD*DD];
__device__ __align__(16) __half g_wkv[2*DD*DD];
__device__ __align__(16) __half g_wo [DD*DD];
__device__ __align__(16) __half g_w1 [DI*DD];
__device__ __align__(16) __half g_w2 [DD*DI];

// ---------------- helpers ----------------
__device__ __forceinline__ float warpSum(float v){
#pragma unroll
    for (int o = 16; o; o >>= 1) v += __shfl_xor_sync(0xffffffffu, v, o);
    return v;
}
__device__ __forceinline__ uint32_t smem_u32(const void* p){
    uint32_t a;
    asm("{ .reg .u64 t; cvta.to.shared.u64 t, %1; cvt.u32.u64 %0, t; }" : "=r"(a) : "l"(p));
    return a;
}
__device__ __forceinline__ void cp16(uint32_t s, const void* g){
    asm volatile("cp.async.cg.shared.global [%0], [%1], 16;" :: "r"(s), "l"(g));
}
__device__ __forceinline__ void cp_commit(){
    asm volatile("cp.async.commit_group;" ::: "memory");
}
__device__ __forceinline__ void cp_wait1(){
    asm volatile("cp.async.wait_group 1;" ::: "memory");
}
__device__ __forceinline__ void cp_wait0(){
    asm volatile("cp.async.wait_group 0;" ::: "memory");
}
__device__ __forceinline__ void mma16(float* c, uint32_t a0, uint32_t a1, uint32_t a2, uint32_t a3,
                                      uint32_t b0, uint32_t b1){
    asm volatile("mma.sync.aligned.m16n8k16.row.col.f32.f16.f16.f32 "
        "{%0,%1,%2,%3}, {%4,%5,%6,%7}, {%8,%9}, {%0,%1,%2,%3};"
        : "+f"(c[0]), "+f"(c[1]), "+f"(c[2]), "+f"(c[3])
        : "r"(a0), "r"(a1), "r"(a2), "r"(a3), "r"(b0), "r"(b1));
}
__device__ __forceinline__ void ldsm4(uint32_t& r0, uint32_t& r1, uint32_t& r2, uint32_t& r3, uint32_t a){
    asm volatile("ldmatrix.sync.aligned.m8n8.x4.shared.b16 {%0,%1,%2,%3}, [%4];"
        : "=r"(r0), "=r"(r1), "=r"(r2), "=r"(r3) : "r"(a));
}
__device__ __forceinline__ uint32_t packh2(float a, float b){
    __half2 h = __floats2half2_rn(a, b);
    return *(uint32_t*)&h;
}

// ---------------- positional encoding ----------------
__global__ void pe_kernel(float* __restrict__ pe){
    int idx = blockIdx.x * 256 + threadIdx.x;
    if (idx >= SS*DD) return;
    int s = idx / DD, d = idx % DD;
    double expo  = (double)(2 * (d / 2)) / (double)DD;
    double denom = pow(10000.0, expo);
    double ang   = (double)s / denom;
    pe[idx] = (float)((d % 2 == 0) ? sin(ang) : cos(ang));
}

__global__ void embed_kernel(const int* __restrict__ tokens,
                             const float* __restrict__ emb,
                             const float* __restrict__ pe,
                             float* __restrict__ x){
    int idx = blockIdx.x * 256 + threadIdx.x;
    int row = idx / DD, d = idx % DD;
    int s = row % SS;
    int t = tokens[row];
    x[idx] = emb[(long long)t * DD + d] * 32.0f + pe[s * DD + d];
}

// ---------------- layernorm: fp32 out (yf) or fp16 out (yh) ----------------
__global__ void ln_kernel(const float* __restrict__ x,
                          const float* __restrict__ g,
                          const float* __restrict__ be,
                          float* __restrict__ yf, __half* __restrict__ yh){
    int row = blockIdx.x, tid = threadIdx.x;
    const float4* xr = (const float4*)(x + (long long)row * DD);
    float4 v = xr[tid];
    float s  = v.x + v.y + v.z + v.w;
    float sq = v.x*v.x + v.y*v.y + v.z*v.z + v.w*v.w;
    __shared__ float sh[16];
    s  = warpSum(s);
    sq = warpSum(sq);
    int wid = tid >> 5, lid = tid & 31;
    if (lid == 0){ sh[wid] = s; sh[wid + 8] = sq; }
    __syncthreads();
    if (wid == 0){
        float a  = (lid < 8) ? sh[lid]     : 0.f;
        float b2 = (lid < 8) ? sh[lid + 8] : 0.f;
        a  = warpSum(a);
        b2 = warpSum(b2);
        if (lid == 0){ sh[0] = a; sh[1] = b2; }
    }
    __syncthreads();
    float mean = sh[0] * (1.0f / DD);
    float var  = sh[1] * (1.0f / DD) - mean * mean;
    float rstd = rsqrtf(var + EPSLN);
    float4 gv = ((const float4*)g)[tid];
    float4 bv = ((const float4*)be)[tid];
    float4 o;
    o.x = (v.x - mean) * rstd * gv.x + bv.x;
    o.y = (v.y - mean) * rstd * gv.y + bv.y;
    o.z = (v.z - mean) * rstd * gv.z + bv.z;
    o.w = (v.w - mean) * rstd * gv.w + bv.w;
    if (yh){
        __half2* hp = (__half2*)(yh + (long long)row * DD + 4 * tid);
        hp[0] = __floats2half2_rn(o.x, o.y);
        hp[1] = __floats2half2_rn(o.z, o.w);
    } else {
        ((float4*)(yf + (long long)row * DD))[tid] = o;
    }
}

// ---------------- weight transpose: dst_h[c][r] = half(src[r][c]) ----------------
__global__ void transpose_kernel(const float* __restrict__ src, __half* __restrict__ dst,
                                 int R, int C){
    __shared__ float t[32][33];
    int c0 = blockIdx.x * 32, r0 = blockIdx.y * 32;
    int x = threadIdx.x, y = threadIdx.y;
#pragma unroll
    for (int j = 0; j < 4; j++)
        t[y + j*8][x] = src[(long long)(r0 + y + j*8) * C + c0 + x];
    __syncthreads();
#pragma unroll
    for (int j = 0; j < 4; j++)
        dst[(long long)(c0 + y + j*8) * R + r0 + x] = __float2half(t[x][y + j*8]);
}

// V transpose: vt[z][d][t] = kv_h[b*512+t][1024 + h*64 + d]
__global__ void vtrans_kernel(const __half* __restrict__ kv, __half* __restrict__ vt){
    __shared__ __half t[32][34];
    int z = blockIdx.z;
    int b = z >> 4, h = z & 15;
    int d0 = blockIdx.x * 32, t0 = blockIdx.y * 32;
    const __half* src = kv + (long long)b * 512 * 2048 + 1024 + h * 64;
    __half* dst = vt + (long long)z * 64 * 512;
    int x = threadIdx.x, y = threadIdx.y;
#pragma unroll
    for (int j = 0; j < 4; j++)
        t[y + j*8][x] = src[(long long)(t0 + y + j*8) * 2048 + d0 + x];
    __syncthreads();
#pragma unroll
    for (int j = 0; j < 4; j++)
        dst[(long long)(d0 + y + j*8) * 512 + t0 + x] = t[x][y + j*8];
}

// ---------------- fused flash attention ----------------
// grid (SS/128, BB*HH); 256 threads = 8 warps, each warp owns 16 q-rows.
// o[token][h*64+d] = softmax(0.125 * Q K^T + mask) @ V
#define QRS 72
#define KRS 72
#define VRS 136
#define FSM ((128*QRS + 2*128*KRS + 2*64*VRS) * 2)

__global__ void __launch_bounds__(256, 1)
flash_kernel(const __half* __restrict__ q, const __half* __restrict__ kv,
             const __half* __restrict__ vt, __half* __restrict__ o,
             const int* __restrict__ lengths)
{
    extern __shared__ __half sm[];
    const uint32_t sQu = smem_u32(sm);
    const uint32_t sKu = sQu + 128*QRS*2;
    const uint32_t sVu = sKu + 2*128*KRS*2;

    const int tid = threadIdx.x, wid = tid >> 5, lid = tid & 31;
    const int tg = lid >> 2, tig = lid & 3;
    const int lid7 = lid & 7;
    const int z = blockIdx.y, b = z >> 4, h = z & 15;
    const int q0 = blockIdx.x * 128;
    const int len = lengths[b];
    const int jmax = (len + 127) >> 7;

    const __half* Qg = q  + (long long)(b * 512 + q0) * 1024 + h * 64;
    const __half* Kg = kv + (long long)b * 512 * 2048 + h * 64;
    const __half* Vg = vt + (long long)z * 64 * 512;

    // stage Q (one group)
#pragma unroll
    for (int i = 0; i < 4; i++){
        int c = tid + 256 * i;
        int row = c >> 3, col = (c & 7) * 8;
        cp16(sQu + (uint32_t)(row * QRS + col) * 2, Qg + (long long)row * 1024 + col);
    }
    cp_commit();

#define KVISSUE(j) do{ \
    int buf_ = (j) & 1; \
    uint32_t kb_ = sKu + (uint32_t)(buf_ * 128 * KRS) * 2; \
    uint32_t vb_ = sVu + (uint32_t)(buf_ * 64 * VRS) * 2; \
    const __half* Kj_ = Kg + (long long)(j) * 128 * 2048; \
    const __half* Vj_ = Vg + (j) * 128; \
    _Pragma("unroll") \
    for (int i = 0; i < 4; i++){ \
        int c = tid + 256 * i; \
        int row = c >> 3, col = (c & 7) * 8; \
        cp16(kb_ + (uint32_t)(row * KRS + col) * 2, Kj_ + (long long)row * 2048 + col); \
    } \
    _Pragma("unroll") \
    for (int i = 0; i < 4; i++){ \
        int c = tid + 256 * i; \
        int row = c >> 4, col = (c & 15) * 8; \
        cp16(vb_ + (uint32_t)(row * VRS + col) * 2, Vj_ + (long long)row * 512 + col); \
    } \
    cp_commit(); \
}while(0)

    KVISSUE(0);

    // fragment addressing
    const uint32_t a_row = (uint32_t)(wid * 16 + ((lid >> 3) & 1) * 8 + lid7);
    const uint32_t a_k   = (uint32_t)((lid >> 4) * 8);
    const uint32_t b_rk  = (uint32_t)(((lid >> 4) & 1) * 8 + lid7);   // row within 16-group
    const uint32_t b_ko  = (uint32_t)(((lid >> 3) & 1) * 8);          // k offset within k16

    float m0 = -1e30f, m1 = -1e30f, l0 = 0.f, l1 = 0.f;
    float oacc[8][4];
#pragma unroll
    for (int f = 0; f < 8; f++)
#pragma unroll
        for (int qd = 0; qd < 4; qd++) oacc[f][qd] = 0.f;

    uint32_t qf[4][4];

    for (int j = 0; j < jmax; j++){
        cp_wait0();
        __syncthreads();
        if (j + 1 < jmax) KVISSUE(j + 1);
        if (j == 0){
#pragma unroll
            for (int k16 = 0; k16 < 4; k16++)
                ldsm4(qf[k16][0], qf[k16][1], qf[k16][2], qf[k16][3],
                      sQu + (uint32_t)(a_row * QRS + a_k + k16 * 16) * 2);
        }
        const uint32_t kb = sKu + (uint32_t)((j & 1) * 128 * KRS) * 2;
        const uint32_t vb = sVu + (uint32_t)((j & 1) * 64 * VRS) * 2;

        // ---- S = Q @ K^T (16 x 128 per warp) ----
        float sacc[16][4];
#pragma unroll
        for (int ni = 0; ni < 16; ni++)
#pragma unroll
            for (int qd = 0; qd < 4; qd++) sacc[ni][qd] = 0.f;
#pragma unroll
        for (int k16 = 0; k16 < 4; k16++){
#pragma unroll
            for (int g = 0; g < 8; g++){
                uint32_t b0, b1, b2, b3;
                ldsm4(b0, b1, b2, b3,
                      kb + (uint32_t)((g * 16 + b_rk) * KRS + b_ko + k16 * 16) * 2);
                mma16(sacc[2*g    ], qf[k16][0], qf[k16][1], qf[k16][2], qf[k16][3], b0, b1);
                mma16(sacc[2*g + 1], qf[k16][0], qf[k16][1], qf[k16][2], qf[k16][3], b2, b3);
            }
        }

        // ---- scale + mask + rowmax ----
        const int lim = len - j * 128;
        float rm0 = -1e30f, rm1 = -1e30f;
#pragma unroll
        for (int ni = 0; ni < 16; ni++){
            int c0 = 8 * ni + 2 * tig;
            sacc[ni][0] *= 0.125f; sacc[ni][1] *= 0.125f;
            sacc[ni][2] *= 0.125f; sacc[ni][3] *= 0.125f;
            if (c0 >= lim)     { sacc[ni][0] = -1e30f; sacc[ni][2] = -1e30f; }
            if (c0 + 1 >= lim) { sacc[ni][1] = -1e30f; sacc[ni][3] = -1e30f; }
            rm0 = fmaxf(rm0, fmaxf(sacc[ni][0], sacc[ni][1]));
            rm1 = fmaxf(rm1, fmaxf(sacc[ni][2], sacc[ni][3]));
        }
        rm0 = fmaxf(rm0, __shfl_xor_sync(0xffffffffu, rm0, 1));
        rm0 = fmaxf(rm0, __shfl_xor_sync(0xffffffffu, rm0, 2));
        rm1 = fmaxf(rm1, __shfl_xor_sync(0xffffffffu, rm1, 1));
        rm1 = fmaxf(rm1, __shfl_xor_sync(0xffffffffu, rm1, 2));

        float mn0 = fmaxf(m0, rm0), mn1 = fmaxf(m1, rm1);
        float al0 = __expf(m0 - mn0), al1 = __expf(m1 - mn1);
        m0 = mn0; m1 = mn1;

        // ---- P = exp(S - m), row sums, pack to half2 ----
        float rs0 = 0.f, rs1 = 0.f;
        uint32_t pa[16], pb[16];
#pragma unroll
        for (int ni = 0; ni < 16; ni++){
            float p0 = __expf(sacc[ni][0] - mn0);
            float p1 = __expf(sacc[ni][1] - mn0);
            float p2 = __expf(sacc[ni][2] - mn1);
            float p3 = __expf(sacc[ni][3] - mn1);
            rs0 += p0 + p1; rs1 += p2 + p3;
            pa[ni] = packh2(p0, p1);
            pb[ni] = packh2(p2, p3);
        }
        rs0 += __shfl_xor_sync(0xffffffffu, rs0, 1);
        rs0 += __shfl_xor_sync(0xffffffffu, rs0, 2);
        rs1 += __shfl_xor_sync(0xffffffffu, rs1, 1);
        rs1 += __shfl_xor_sync(0xffffffffu, rs1, 2);
        l0 = l0 * al0 + rs0;
        l1 = l1 * al1 + rs1;

        // ---- rescale O, then O += P @ V ----
#pragma unroll
        for (int f = 0; f < 8; f++){
            oacc[f][0] *= al0; oacc[f][1] *= al0;
            oacc[f][2] *= al1; oacc[f][3] *= al1;
        }
#pragma unroll
        for (int j2 = 0; j2 < 8; j2++){     // k16 over keys
#pragma unroll
            for (int gd = 0; gd < 4; gd++){ // d 16-groups
                uint32_t b0, b1, b2, b3;
                ldsm4(b0, b1, b2, b3,
                      vb + (uint32_t)((gd * 16 + b_rk) * VRS + b_ko + j2 * 16) * 2);
                mma16(oacc[2*gd    ], pa[2*j2], pb[2*j2], pa[2*j2+1], pb[2*j2+1], b0, b1);
                mma16(oacc[2*gd + 1], pa[2*j2], pb[2*j2], pa[2*j2+1], pb[2*j2+1], b2, b3);
            }
        }
    }
#undef KVISSUE

    // ---- normalize + write ----
    float inv0 = 1.0f / l0, inv1 = 1.0f / l1;
    int r0 = q0 + wid * 16 + tg;
    long long t0 = (long long)(b * 512 + r0) * 1024 + h * 64;
    long long t1 = t0 + 8 * 1024;
#pragma unroll
    for (int f = 0; f < 8; f++){
        int col = 8 * f + 2 * tig;
        *(__half2*)(o + t0 + col) = __floats2half2_rn(oacc[f][0] * inv0, oacc[f][1] * inv0);
        *(__half2*)(o + t1 + col) = __floats2half2_rn(oacc[f][2] * inv1, oacc[f][3] * inv1);
    }
}

// ---------------- fp16 mma.sync GEMM, ldmatrix + 3-stage cp.async, 1 barrier/tile ----
template<int BN>
__global__ void __launch_bounds__(256, 2)
hgemm(int K,
      const __half* __restrict__ A, int lda,
      const __half* __restrict__ B, int ldb,
      float* __restrict__ Cf, __half* __restrict__ Ch, int ldc,
      const float* __restrict__ bias, const float* __restrict__ res,
      float alpha, int relu)
{
    constexpr int BM  = 128;
    constexpr int RSh = 40;
    constexpr int STG = (BM + BN) * RSh;
    constexpr int NF  = BN / 16;
    constexpr int NBI = (BN * 4) / 256;

    extern __shared__ __half smp[];

    const int tid = threadIdx.x;
    const int wid = tid >> 5, lid = tid & 31;
    const int wm = wid >> 1, wn = wid & 1;
    const int tg = lid >> 2, tig = lid & 3;

    const int m0 = blockIdx.y * BM;
    const int n0 = blockIdx.x * BN;
    const int nst = K >> 5;

    const int srow = tid >> 2;
    const int chnk = tid & 3;
    const __half* Ab = A + (long long)(m0 + srow) * lda + chnk * 8;
    const __half* Bb = B + (long long)(n0 + srow) * ldb + chnk * 8;
    const uint32_t smem0 = smem_u32(smp);
    const uint32_t aoff = (uint32_t)(srow * RSh + chnk * 8) * 2;
    const uint32_t boff = (uint32_t)(BM * RSh + srow * RSh + chnk * 8) * 2;

    const int lid7 = lid & 7;
    const uint32_t a_row = wm * 32 + ((lid >> 3) & 1) * 8 + lid7;
    const uint32_t a_kof = (lid >> 4) * 8;
    const uint32_t a_base = (uint32_t)(a_row * RSh + a_kof) * 2;
    const uint32_t b_row = wn * (BN / 2) + ((lid >> 4) & 1) * 8 + lid7;
    const uint32_t b_kof = ((lid >> 3) & 1) * 8;
    const uint32_t b_base = (uint32_t)((BM + b_row) * RSh + b_kof) * 2;

    float acc[2][NF][4];
#pragma unroll
    for (int i = 0; i < 2; i++)
#pragma unroll
        for (int j = 0; j < NF; j++)
#pragma unroll
            for (int qd = 0; qd < 4; qd++) acc[i][j][qd] = 0.f;

#define ISSUE(sidx) do{ \
    uint32_t sb = smem0 + (uint32_t)(((sidx) % 3) * STG) * 2; \
    const __half* Ag = Ab + (sidx) * 32; \
    const __half* Bg = Bb + (sidx) * 32; \
    _Pragma("unroll") \
    for (int i = 0; i < 2; i++) \
        cp16(sb + aoff + (uint32_t)(i * 64 * RSh) * 2, Ag + (long long)i * 64 * lda); \
    _Pragma("unroll") \
    for (int i = 0; i < NBI; i++) \
        cp16(sb + boff + (uint32_t)(i * 64 * RSh) * 2, Bg + (long long)i * 64 * ldb); \
    cp_commit(); \
}while(0)

    ISSUE(0);
    if (nst > 1) ISSUE(1);

    for (int s = 0; s < nst; s++){
        if (s + 1 < nst) cp_wait1(); else cp_wait0();
        __syncthreads();
        if (s + 2 < nst) ISSUE(s + 2);

        const uint32_t stg = smem0 + (uint32_t)((s % 3) * STG) * 2;
#pragma unroll
        for (int k16 = 0; k16 < 2; k16++){
            const uint32_t kby = (uint32_t)(k16 * 16) * 2;
            uint32_t af[2][4];
#pragma unroll
            for (int mi = 0; mi < 2; mi++)
                ldsm4(af[mi][0], af[mi][1], af[mi][2], af[mi][3],
                      stg + a_base + (uint32_t)(mi * 16 * RSh) * 2 + kby);
#pragma unroll
            for (int nip = 0; nip < NF / 2; nip++){
                uint32_t b0, b1, b2, b3;
                ldsm4(b0, b1, b2, b3,
                      stg + b_base + (uint32_t)(nip * 16 * RSh) * 2 + kby);
#pragma unroll
                for (int mi = 0; mi < 2; mi++){
                    mma16(acc[mi][2*nip    ], af[mi][0], af[mi][1], af[mi][2], af[mi][3], b0, b1);
                    mma16(acc[mi][2*nip + 1], af[mi][0], af[mi][1], af[mi][2], af[mi][3], b2, b3);
                }
            }
        }
    }
#undef ISSUE

    // ---- epilogue ----
#pragma unroll
    for (int mi = 0; mi < 2; mi++){
        int r0 = m0 + wm * 32 + mi * 16 + tg;
#pragma unroll
        for (int ni = 0; ni < NF; ni++){
            int cc = n0 + wn * (BN / 2) + ni * 8 + tig * 2;
            float bx = 0.f, by = 0.f;
            if (bias){ bx = bias[cc]; by = bias[cc + 1]; }
#pragma unroll
            for (int hrow = 0; hrow < 2; hrow++){
                int r = r0 + hrow * 8;
                float v0 = acc[mi][ni][hrow * 2 + 0] * alpha + bx;
                float v1 = acc[mi][ni][hrow * 2 + 1] * alpha + by;
                if (relu){ v0 = fmaxf(v0, 0.f); v1 = fmaxf(v1, 0.f); }
                long long g = (long long)r * ldc + cc;
                if (res){
                    float2 rv = *(const float2*)(res + g);
                    v0 += rv.x; v1 += rv.y;
                }
                if (Ch){
                    *(__half2*)(Ch + g) = __floats2half2_rn(v0, v1);
                } else {
                    float2 o; o.x = v0; o.y = v1;
                    *(float2*)(Cf + g) = o;
                }
            }
        }
    }
}

// ---------------- host side ----------------
#define SMH128 (3 * (128 + 128) * 40 * 2)

static void big_gemm(const __half* A, int lda, const __half* Bt, int ldb,
                     float* Cf, __half* Ch, int ldc,
                     const float* bias, const float* res,
                     int M, int N, int K, int relu){
    dim3 grid(N / 128, M / 128, 1);
    hgemm<128><<<grid, 256, SMH128>>>(K, A, lda, Bt, ldb, Cf, Ch, ldc, bias, res, 1.0f, relu);
}

extern "C" void kernel_launch(void* const* d_in, const int* in_sizes, int n_in,
                              void* d_out, int out_size){
    const int*   tokens    = (const int*)  d_in[0];
    const int*   lengths   = (const int*)  d_in[1];
    const float* emb       = (const float*)d_in[2];
    const float* Wq        = (const float*)d_in[3];
    const float* bq        = (const float*)d_in[4];
    const float* Wkv       = (const float*)d_in[5];
    const float* bkv       = (const float*)d_in[6];
    const float* Wo        = (const float*)d_in[7];
    const float* bo        = (const float*)d_in[8];
    const float* ln_attn_g = (const float*)d_in[9];
    const float* ln_attn_b = (const float*)d_in[10];
    const float* W1        = (const float*)d_in[11];
    const float* b1        = (const float*)d_in[12];
    const float* W2        = (const float*)d_in[13];
    const float* b2        = (const float*)d_in[14];
    const float* ln_ffn_g  = (const float*)d_in[15];
    const float* ln_ffn_b  = (const float*)d_in[16];
    const float* ln_f_g    = (const float*)d_in[17];
    const float* ln_f_b    = (const float*)d_in[18];
    float* out = (float*)d_out;

    cudaFuncSetAttribute((const void*)hgemm<128>, cudaFuncAttributeMaxDynamicSharedMemorySize, SMH128);
    cudaFuncSetAttribute((const void*)flash_kernel, cudaFuncAttributeMaxDynamicSharedMemorySize, FSM);

    float *xb, *peb;
    __half *hb, *qb, *kvb, *ob, *fb, *vtb;
    __half *wqt, *wkvt, *wot, *w1t, *w2t;
    cudaGetSymbolAddress((void**)&xb,   g_x);
    cudaGetSymbolAddress((void**)&peb,  g_pe);
    cudaGetSymbolAddress((void**)&hb,   g_h);
    cudaGetSymbolAddress((void**)&qb,   g_q);
    cudaGetSymbolAddress((void**)&kvb,  g_kv);
    cudaGetSymbolAddress((void**)&ob,   g_o);
    cudaGetSymbolAddress((void**)&fb,   g_ffn);
    cudaGetSymbolAddress((void**)&vtb,  g_vt);
    cudaGetSymbolAddress((void**)&wqt,  g_wq);
    cudaGetSymbolAddress((void**)&wkvt, g_wkv);
    cudaGetSymbolAddress((void**)&wot,  g_wo);
    cudaGetSymbolAddress((void**)&w1t,  g_w1);
    cudaGetSymbolAddress((void**)&w2t,  g_w2);

    pe_kernel<<<(SS*DD + 255)/256, 256>>>(peb);
    embed_kernel<<<(NTOK*DD)/256, 256>>>(tokens, emb, peb, xb);

    dim3 tb(32, 8);
    for (int l = 0; l < LL; l++){
        // ---- attention sublayer ----
        ln_kernel<<<NTOK, 256>>>(xb, ln_attn_g + l*DD, ln_attn_b + l*DD, nullptr, hb);

        transpose_kernel<<<dim3(DD/32,   DD/32), tb>>>(Wq  + (long long)l*DD*DD,   wqt,  DD, DD);
        transpose_kernel<<<dim3(2*DD/32, DD/32), tb>>>(Wkv + (long long)l*DD*2*DD, wkvt, DD, 2*DD);

        big_gemm(hb, DD, wqt,  DD, nullptr, qb,  DD,   bq  + l*DD,   nullptr, NTOK, DD,   DD, 0);
        big_gemm(hb, DD, wkvt, DD, nullptr, kvb, 2*DD, bkv + l*2*DD, nullptr, NTOK, 2*DD, DD, 0);

        vtrans_kernel<<<dim3(2, 16, BB*HH), tb>>>(kvb, vtb);
        flash_kernel<<<dim3(SS/128, BB*HH), 256, FSM>>>(qb, kvb, vtb, ob, lengths);

        // x = x + o @ Wo + bo
        transpose_kernel<<<dim3(DD/32, DD/32), tb>>>(Wo + (long long)l*DD*DD, wot, DD, DD);
        big_gemm(ob, DD, wot, DD, xb, nullptr, DD, bo + l*DD, xb, NTOK, DD, DD, 0);

        // ---- FFN sublayer ----
        ln_kernel<<<NTOK, 256>>>(xb, ln_ffn_g + l*DD, ln_ffn_b + l*DD, nullptr, hb);
        transpose_kernel<<<dim3(DI/32, DD/32), tb>>>(W1 + (long long)l*DD*DI, w1t, DD, DI);
        big_gemm(hb, DD, w1t, DD, nullptr, fb, DI, b1 + l*DI, nullptr, NTOK, DI, DD, 1);
        transpose_kernel<<<dim3(DD/32, DI/32), tb>>>(W2 + (long long)l*DI*DD, w2t, DI, DD);
        big_gemm(fb, DI, w2t, DI, xb, nullptr, DD, b2 + l*DD, xb, NTOK, DD, DI, 0);
    }

    ln_kernel<<<NTOK, 256>>>(xb, ln_f_g, ln_f_b, out, nullptr);
}

// round 14
// speedup vs baseline: 3.3578x; 1.0657x over previous
#include <cuda_runtime.h>
#include <cuda_fp16.h>
#include <math.h>
#include <stdint.h>

#define BB 8
#define SS 512
#define DD 1024
#define HH 16
#define DQh 64
#define DI 4096
#define LL 6
#define NTOK (BB*SS)
#define EPSLN 1e-5f

// ---------------- device scratch ----------------
__device__ __align__(16) float  g_x  [NTOK*DD];
__device__ __align__(16) float  g_pe [SS*DD];
__device__ __align__(16) __half g_h  [NTOK*DD];
__device__ __align__(16) __half g_q  [NTOK*DD];
__device__ __align__(16) __half g_kv [NTOK*2*DD];
__device__ __align__(16) __half g_o  [NTOK*DD];
__device__ __align__(16) __half g_ffn[NTOK*DI];
__device__ __align__(16) __half g_wq [LL*DD*DD];
__device__ __align__(16) __half g_wkv[LL*DD*2*DD];
__device__ __align__(16) __half g_wo [LL*DD*DD];
__device__ __align__(16) __half g_w1 [LL*DD*DI];
__device__ __align__(16) __half g_w2 [LL*DI*DD];

// ---------------- helpers ----------------
__device__ __forceinline__ float warpSum(float v){
#pragma unroll
    for (int o = 16; o; o >>= 1) v += __shfl_xor_sync(0xffffffffu, v, o);
    return v;
}
__device__ __forceinline__ uint32_t smem_u32(const void* p){
    uint32_t a;
    asm("{ .reg .u64 t; cvta.to.shared.u64 t, %1; cvt.u32.u64 %0, t; }" : "=r"(a) : "l"(p));
    return a;
}
__device__ __forceinline__ void cp16(uint32_t s, const void* g){
    asm volatile("cp.async.cg.shared.global [%0], [%1], 16;" :: "r"(s), "l"(g));
}
__device__ __forceinline__ void cp_commit(){
    asm volatile("cp.async.commit_group;" ::: "memory");
}
__device__ __forceinline__ void cp_wait1(){
    asm volatile("cp.async.wait_group 1;" ::: "memory");
}
__device__ __forceinline__ void cp_wait0(){
    asm volatile("cp.async.wait_group 0;" ::: "memory");
}
__device__ __forceinline__ void mma16(float* c, uint32_t a0, uint32_t a1, uint32_t a2, uint32_t a3,
                                      uint32_t b0, uint32_t b1){
    asm volatile("mma.sync.aligned.m16n8k16.row.col.f32.f16.f16.f32 "
        "{%0,%1,%2,%3}, {%4,%5,%6,%7}, {%8,%9}, {%0,%1,%2,%3};"
        : "+f"(c[0]), "+f"(c[1]), "+f"(c[2]), "+f"(c[3])
        : "r"(a0), "r"(a1), "r"(a2), "r"(a3), "r"(b0), "r"(b1));
}
__device__ __forceinline__ void ldsm4(uint32_t& r0, uint32_t& r1, uint32_t& r2, uint32_t& r3, uint32_t a){
    asm volatile("ldmatrix.sync.aligned.m8n8.x4.shared.b16 {%0,%1,%2,%3}, [%4];"
        : "=r"(r0), "=r"(r1), "=r"(r2), "=r"(r3) : "r"(a));
}
__device__ __forceinline__ void ldsm4t(uint32_t& r0, uint32_t& r1, uint32_t& r2, uint32_t& r3, uint32_t a){
    asm volatile("ldmatrix.sync.aligned.m8n8.x4.trans.shared.b16 {%0,%1,%2,%3}, [%4];"
        : "=r"(r0), "=r"(r1), "=r"(r2), "=r"(r3) : "r"(a));
}
__device__ __forceinline__ uint32_t packh2(float a, float b){
    __half2 h = __floats2half2_rn(a, b);
    return *(uint32_t*)&h;
}

// ---------------- fp32 -> fp16 streaming convert ----------------
__global__ void cvt_kernel(const float* __restrict__ src, __half* __restrict__ dst, int n4){
    int i = blockIdx.x * 256 + threadIdx.x;
    if (i >= n4) return;
    float4 v = ((const float4*)src)[i];
    __half2 h0 = __floats2half2_rn(v.x, v.y);
    __half2 h1 = __floats2half2_rn(v.z, v.w);
    uint2 o; o.x = *(uint32_t*)&h0; o.y = *(uint32_t*)&h1;
    ((uint2*)dst)[i] = o;
}

// ---------------- positional encoding ----------------
__global__ void pe_kernel(float* __restrict__ pe){
    int idx = blockIdx.x * 256 + threadIdx.x;
    if (idx >= SS*DD) return;
    int s = idx / DD, d = idx % DD;
    double expo  = (double)(2 * (d / 2)) / (double)DD;
    double denom = pow(10000.0, expo);
    double ang   = (double)s / denom;
    pe[idx] = (float)((d % 2 == 0) ? sin(ang) : cos(ang));
}

__global__ void embed_kernel(const int* __restrict__ tokens,
                             const float* __restrict__ emb,
                             const float* __restrict__ pe,
                             float* __restrict__ x){
    int idx = blockIdx.x * 256 + threadIdx.x;
    int row = idx / DD, d = idx % DD;
    int s = row % SS;
    int t = tokens[row];
    x[idx] = emb[(long long)t * DD + d] * 32.0f + pe[s * DD + d];
}

// ---------------- layernorm: fp32 out (yf) or fp16 out (yh) ----------------
__global__ void ln_kernel(const float* __restrict__ x,
                          const float* __restrict__ g,
                          const float* __restrict__ be,
                          float* __restrict__ yf, __half* __restrict__ yh){
    int row = blockIdx.x, tid = threadIdx.x;
    const float4* xr = (const float4*)(x + (long long)row * DD);
    float4 v = xr[tid];
    float s  = v.x + v.y + v.z + v.w;
    float sq = v.x*v.x + v.y*v.y + v.z*v.z + v.w*v.w;
    __shared__ float sh[16];
    s  = warpSum(s);
    sq = warpSum(sq);
    int wid = tid >> 5, lid = tid & 31;
    if (lid == 0){ sh[wid] = s; sh[wid + 8] = sq; }
    __syncthreads();
    if (wid == 0){
        float a  = (lid < 8) ? sh[lid]     : 0.f;
        float b2 = (lid < 8) ? sh[lid + 8] : 0.f;
        a  = warpSum(a);
        b2 = warpSum(b2);
        if (lid == 0){ sh[0] = a; sh[1] = b2; }
    }
    __syncthreads();
    float mean = sh[0] * (1.0f / DD);
    float var  = sh[1] * (1.0f / DD) - mean * mean;
    float rstd = rsqrtf(var + EPSLN);
    float4 gv = ((const float4*)g)[tid];
    float4 bv = ((const float4*)be)[tid];
    float4 o;
    o.x = (v.x - mean) * rstd * gv.x + bv.x;
    o.y = (v.y - mean) * rstd * gv.y + bv.y;
    o.z = (v.z - mean) * rstd * gv.z + bv.z;
    o.w = (v.w - mean) * rstd * gv.w + bv.w;
    if (yh){
        __half2* hp = (__half2*)(yh + (long long)row * DD + 4 * tid);
        hp[0] = __floats2half2_rn(o.x, o.y);
        hp[1] = __floats2half2_rn(o.z, o.w);
    } else {
        ((float4*)(yf + (long long)row * DD))[tid] = o;
    }
}

// ---------------- fused flash attention ----------------
// grid (SS/128, BB*HH); 256 threads = 8 warps, each warp owns 16 q-rows.
#define QRS 72
#define KRS 72
#define VRS 72
#define FSM ((128*QRS + 2*128*KRS + 2*128*VRS) * 2)

__global__ void __launch_bounds__(256, 1)
flash_kernel(const __half* __restrict__ q, const __half* __restrict__ kv,
             __half* __restrict__ o, const int* __restrict__ lengths)
{
    extern __shared__ __half sm[];
    const uint32_t sQu = smem_u32(sm);
    const uint32_t sKu = sQu + 128*QRS*2;
    const uint32_t sVu = sKu + 2*128*KRS*2;

    const int tid = threadIdx.x, wid = tid >> 5, lid = tid & 31;
    const int tg = lid >> 2, tig = lid & 3;
    const int lid7 = lid & 7;
    const int z = blockIdx.y, b = z >> 4, h = z & 15;
    const int q0 = blockIdx.x * 128;
    const int len = lengths[b];
    const int jmax = (len + 127) >> 7;

    const __half* Qg = q  + (long long)(b * 512 + q0) * 1024 + h * 64;
    const __half* Kg = kv + (long long)b * 512 * 2048 + h * 64;   // V at +1024

    // stage Q
#pragma unroll
    for (int i = 0; i < 4; i++){
        int c = tid + 256 * i;
        int row = c >> 3, col = (c & 7) * 8;
        cp16(sQu + (uint32_t)(row * QRS + col) * 2, Qg + (long long)row * 1024 + col);
    }
    cp_commit();

#define KVISSUE(j) do{ \
    int buf_ = (j) & 1; \
    uint32_t kb_ = sKu + (uint32_t)(buf_ * 128 * KRS) * 2; \
    uint32_t vb_ = sVu + (uint32_t)(buf_ * 128 * VRS) * 2; \
    const __half* Kj_ = Kg + (long long)(j) * 128 * 2048; \
    _Pragma("unroll") \
    for (int i = 0; i < 4; i++){ \
        int c = tid + 256 * i; \
        int row = c >> 3, col = (c & 7) * 8; \
        cp16(kb_ + (uint32_t)(row * KRS + col) * 2, Kj_ + (long long)row * 2048 + col); \
        cp16(vb_ + (uint32_t)(row * VRS + col) * 2, Kj_ + 1024 + (long long)row * 2048 + col); \
    } \
    cp_commit(); \
}while(0)

    KVISSUE(0);

    // fragment addressing
    const uint32_t a_row = (uint32_t)(wid * 16 + ((lid >> 3) & 1) * 8 + lid7);
    const uint32_t a_k   = (uint32_t)((lid >> 4) * 8);
    const uint32_t b_rk  = (uint32_t)(((lid >> 4) & 1) * 8 + lid7);
    const uint32_t b_ko  = (uint32_t)(((lid >> 3) & 1) * 8);
    // trans-ldsm (V): rows = k(t), col = n(d)
    const uint32_t vt_row = (uint32_t)(lid & 15);
    const uint32_t vt_col = (uint32_t)((lid >> 4) * 8);

    float m0 = -1e30f, m1 = -1e30f, l0 = 0.f, l1 = 0.f;
    float oacc[8][4];
#pragma unroll
    for (int f = 0; f < 8; f++)
#pragma unroll
        for (int qd = 0; qd < 4; qd++) oacc[f][qd] = 0.f;

    uint32_t qf[4][4];

    for (int j = 0; j < jmax; j++){
        cp_wait0();
        __syncthreads();
        if (j + 1 < jmax) KVISSUE(j + 1);
        if (j == 0){
#pragma unroll
            for (int k16 = 0; k16 < 4; k16++)
                ldsm4(qf[k16][0], qf[k16][1], qf[k16][2], qf[k16][3],
                      sQu + (uint32_t)(a_row * QRS + a_k + k16 * 16) * 2);
        }
        const uint32_t kb = sKu + (uint32_t)((j & 1) * 128 * KRS) * 2;
        const uint32_t vb = sVu + (uint32_t)((j & 1) * 128 * VRS) * 2;

        // ---- S = Q @ K^T ----
        float sacc[16][4];
#pragma unroll
        for (int ni = 0; ni < 16; ni++)
#pragma unroll
            for (int qd = 0; qd < 4; qd++) sacc[ni][qd] = 0.f;
#pragma unroll
        for (int k16 = 0; k16 < 4; k16++){
#pragma unroll
            for (int g = 0; g < 8; g++){
                uint32_t b0, b1, b2, b3;
                ldsm4(b0, b1, b2, b3,
                      kb + (uint32_t)((g * 16 + b_rk) * KRS + b_ko + k16 * 16) * 2);
                mma16(sacc[2*g    ], qf[k16][0], qf[k16][1], qf[k16][2], qf[k16][3], b0, b1);
                mma16(sacc[2*g + 1], qf[k16][0], qf[k16][1], qf[k16][2], qf[k16][3], b2, b3);
            }
        }

        // ---- scale + mask + rowmax ----
        const int lim = len - j * 128;
        float rm0 = -1e30f, rm1 = -1e30f;
#pragma unroll
        for (int ni = 0; ni < 16; ni++){
            int c0 = 8 * ni + 2 * tig;
            sacc[ni][0] *= 0.125f; sacc[ni][1] *= 0.125f;
            sacc[ni][2] *= 0.125f; sacc[ni][3] *= 0.125f;
            if (c0 >= lim)     { sacc[ni][0] = -1e30f; sacc[ni][2] = -1e30f; }
            if (c0 + 1 >= lim) { sacc[ni][1] = -1e30f; sacc[ni][3] = -1e30f; }
            rm0 = fmaxf(rm0, fmaxf(sacc[ni][0], sacc[ni][1]));
            rm1 = fmaxf(rm1, fmaxf(sacc[ni][2], sacc[ni][3]));
        }
        rm0 = fmaxf(rm0, __shfl_xor_sync(0xffffffffu, rm0, 1));
        rm0 = fmaxf(rm0, __shfl_xor_sync(0xffffffffu, rm0, 2));
        rm1 = fmaxf(rm1, __shfl_xor_sync(0xffffffffu, rm1, 1));
        rm1 = fmaxf(rm1, __shfl_xor_sync(0xffffffffu, rm1, 2));

        float mn0 = fmaxf(m0, rm0), mn1 = fmaxf(m1, rm1);
        float al0 = __expf(m0 - mn0), al1 = __expf(m1 - mn1);
        m0 = mn0; m1 = mn1;

        // ---- P = exp(S - m), row sums, pack ----
        float rs0 = 0.f, rs1 = 0.f;
        uint32_t pa[16], pb[16];
#pragma unroll
        for (int ni = 0; ni < 16; ni++){
            float p0 = __expf(sacc[ni][0] - mn0);
            float p1 = __expf(sacc[ni][1] - mn0);
            float p2 = __expf(sacc[ni][2] - mn1);
            float p3 = __expf(sacc[ni][3] - mn1);
            rs0 += p0 + p1; rs1 += p2 + p3;
            pa[ni] = packh2(p0, p1);
            pb[ni] = packh2(p2, p3);
        }
        rs0 += __shfl_xor_sync(0xffffffffu, rs0, 1);
        rs0 += __shfl_xor_sync(0xffffffffu, rs0, 2);
        rs1 += __shfl_xor_sync(0xffffffffu, rs1, 1);
        rs1 += __shfl_xor_sync(0xffffffffu, rs1, 2);
        l0 = l0 * al0 + rs0;
        l1 = l1 * al1 + rs1;

        // ---- rescale O, then O += P @ V (trans-ldsm from [t][d]) ----
#pragma unroll
        for (int f = 0; f < 8; f++){
            oacc[f][0] *= al0; oacc[f][1] *= al0;
            oacc[f][2] *= al1; oacc[f][3] *= al1;
        }
#pragma unroll
        for (int j2 = 0; j2 < 8; j2++){
#pragma unroll
            for (int gd = 0; gd < 4; gd++){
                uint32_t b0, b1, b2, b3;
                ldsm4t(b0, b1, b2, b3,
                       vb + (uint32_t)((j2 * 16 + vt_row) * VRS + gd * 16 + vt_col) * 2);
                mma16(oacc[2*gd    ], pa[2*j2], pb[2*j2], pa[2*j2+1], pb[2*j2+1], b0, b1);
                mma16(oacc[2*gd + 1], pa[2*j2], pb[2*j2], pa[2*j2+1], pb[2*j2+1], b2, b3);
            }
        }
    }
#undef KVISSUE

    // ---- normalize + write ----
    float inv0 = 1.0f / l0, inv1 = 1.0f / l1;
    int r0 = q0 + wid * 16 + tg;
    long long t0 = (long long)(b * 512 + r0) * 1024 + h * 64;
    long long t1 = t0 + 8 * 1024;
#pragma unroll
    for (int f = 0; f < 8; f++){
        int col = 8 * f + 2 * tig;
        *(__half2*)(o + t0 + col) = __floats2half2_rn(oacc[f][0] * inv0, oacc[f][1] * inv0);
        *(__half2*)(o + t1 + col) = __floats2half2_rn(oacc[f][2] * inv1, oacc[f][3] * inv1);
    }
}

// ---------------- fp16 GEMM: A [M][K], B [K][N] (natural weights), trans-ldsm B ----
#define RSA 40
#define RSB 136
#define ASZ (128*RSA)
#define STGH (ASZ + 32*RSB)
#define SMH (3 * STGH * 2)

__global__ void __launch_bounds__(256, 2)
hgemm(int K,
      const __half* __restrict__ A, int lda,
      const __half* __restrict__ B, int ldb,
      float* __restrict__ Cf, __half* __restrict__ Ch, int ldc,
      const float* __restrict__ bias, const float* __restrict__ res,
      int relu)
{
    extern __shared__ __half smp[];

    const int tid = threadIdx.x;
    const int wid = tid >> 5, lid = tid & 31;
    const int wm = wid >> 1, wn = wid & 1;
    const int tg = lid >> 2, tig = lid & 3;
    const int lid7 = lid & 7;

    const int m0 = blockIdx.y * 128;
    const int n0 = blockIdx.x * 128;
    const int nst = K >> 5;

    // A staging: 128 rows x 32 halves (4 chunks of 8)
    const int arow = tid >> 2, ach = tid & 3;
    const __half* Ab = A + (long long)(m0 + arow) * lda + ach * 8;
    // B staging: 32 rows x 128 halves (16 chunks of 8) -> 2 per thread
    const int brow = tid >> 3, bch = tid & 7;
    const __half* Bb = B + (long long)brow * ldb + n0 + bch * 8;

    const uint32_t smem0 = smem_u32(smp);
    const uint32_t aoff = (uint32_t)(arow * RSA + ach * 8) * 2;
    const uint32_t boff = (uint32_t)(ASZ + brow * RSB + bch * 8) * 2;

    // A frags (non-trans)
    const uint32_t a_base = (uint32_t)((wm * 32 + ((lid >> 3) & 1) * 8 + lid7) * RSA
                                       + (lid >> 4) * 8) * 2;
    // B frags (trans): rows = k, col = n
    const uint32_t bt_base = (uint32_t)(ASZ + (lid & 15) * RSB + wn * 64 + (lid >> 4) * 8) * 2;

    float acc[2][8][4];
#pragma unroll
    for (int i = 0; i < 2; i++)
#pragma unroll
        for (int j = 0; j < 8; j++)
#pragma unroll
            for (int qd = 0; qd < 4; qd++) acc[i][j][qd] = 0.f;

#define ISSUE(sidx) do{ \
    uint32_t sb = smem0 + (uint32_t)(((sidx) % 3) * STGH) * 2; \
    const __half* Ag = Ab + (sidx) * 32; \
    const __half* Bg = Bb + (long long)(sidx) * 32 * ldb; \
    cp16(sb + aoff, Ag); \
    cp16(sb + aoff + (uint32_t)(64 * RSA) * 2, Ag + (long long)64 * lda); \
    cp16(sb + boff, Bg); \
    cp16(sb + boff + 128, Bg + 64); \
    cp_commit(); \
}while(0)

    ISSUE(0);
    if (nst > 1) ISSUE(1);

    for (int s = 0; s < nst; s++){
        if (s + 1 < nst) cp_wait1(); else cp_wait0();
        __syncthreads();
        if (s + 2 < nst) ISSUE(s + 2);

        const uint32_t stg = smem0 + (uint32_t)((s % 3) * STGH) * 2;
#pragma unroll
        for (int k16 = 0; k16 < 2; k16++){
            uint32_t af[2][4];
#pragma unroll
            for (int mi = 0; mi < 2; mi++)
                ldsm4(af[mi][0], af[mi][1], af[mi][2], af[mi][3],
                      stg + a_base + (uint32_t)(mi * 16 * RSA + k16 * 16) * 2);
#pragma unroll
            for (int nip = 0; nip < 4; nip++){
                uint32_t b0, b1, b2, b3;
                ldsm4t(b0, b1, b2, b3,
                       stg + bt_base + (uint32_t)(k16 * 16 * RSB + nip * 16) * 2);
#pragma unroll
                for (int mi = 0; mi < 2; mi++){
                    mma16(acc[mi][2*nip    ], af[mi][0], af[mi][1], af[mi][2], af[mi][3], b0, b1);
                    mma16(acc[mi][2*nip + 1], af[mi][0], af[mi][1], af[mi][2], af[mi][3], b2, b3);
                }
            }
        }
    }
#undef ISSUE

    // ---- epilogue ----
#pragma unroll
    for (int mi = 0; mi < 2; mi++){
        int r0 = m0 + wm * 32 + mi * 16 + tg;
#pragma unroll
        for (int ni = 0; ni < 8; ni++){
            int cc = n0 + wn * 64 + ni * 8 + tig * 2;
            float bx = 0.f, by = 0.f;
            if (bias){ bx = bias[cc]; by = bias[cc + 1]; }
#pragma unroll
            for (int hrow = 0; hrow < 2; hrow++){
                int r = r0 + hrow * 8;
                float v0 = acc[mi][ni][hrow * 2 + 0] + bx;
                float v1 = acc[mi][ni][hrow * 2 + 1] + by;
                if (relu){ v0 = fmaxf(v0, 0.f); v1 = fmaxf(v1, 0.f); }
                long long g = (long long)r * ldc + cc;
                if (res){
                    float2 rv = *(const float2*)(res + g);
                    v0 += rv.x; v1 += rv.y;
                }
                if (Ch){
                    *(__half2*)(Ch + g) = __floats2half2_rn(v0, v1);
                } else {
                    float2 o; o.x = v0; o.y = v1;
                    *(float2*)(Cf + g) = o;
                }
            }
        }
    }
}

// ---------------- host side ----------------
static void big_gemm(const __half* A, int lda, const __half* B, int ldb,
                     float* Cf, __half* Ch, int ldc,
                     const float* bias, const float* res,
                     int M, int N, int K, int relu){
    dim3 grid(N / 128, M / 128, 1);
    hgemm<<<grid, 256, SMH>>>(K, A, lda, B, ldb, Cf, Ch, ldc, bias, res, relu);
}

static void cvt(const float* src, __half* dst, long long n){
    int n4 = (int)(n / 4);
    cvt_kernel<<<(n4 + 255) / 256, 256>>>(src, dst, n4);
}

extern "C" void kernel_launch(void* const* d_in, const int* in_sizes, int n_in,
                              void* d_out, int out_size){
    const int*   tokens    = (const int*)  d_in[0];
    const int*   lengths   = (const int*)  d_in[1];
    const float* emb       = (const float*)d_in[2];
    const float* Wq        = (const float*)d_in[3];
    const float* bq        = (const float*)d_in[4];
    const float* Wkv       = (const float*)d_in[5];
    const float* bkv       = (const float*)d_in[6];
    const float* Wo        = (const float*)d_in[7];
    const float* bo        = (const float*)d_in[8];
    const float* ln_attn_g = (const float*)d_in[9];
    const float* ln_attn_b = (const float*)d_in[10];
    const float* W1        = (const float*)d_in[11];
    const float* b1        = (const float*)d_in[12];
    const float* W2        = (const float*)d_in[13];
    const float* b2        = (const float*)d_in[14];
    const float* ln_ffn_g  = (const float*)d_in[15];
    const float* ln_ffn_b  = (const float*)d_in[16];
    const float* ln_f_g    = (const float*)d_in[17];
    const float* ln_f_b    = (const float*)d_in[18];
    float* out = (float*)d_out;

    cudaFuncSetAttribute((const void*)hgemm, cudaFuncAttributeMaxDynamicSharedMemorySize, SMH);
    cudaFuncSetAttribute((const void*)flash_kernel, cudaFuncAttributeMaxDynamicSharedMemorySize, FSM);

    float *xb, *peb;
    __half *hb, *qb, *kvb, *ob, *fb;
    __half *wqh, *wkvh, *woh, *w1h, *w2h;
    cudaGetSymbolAddress((void**)&xb,   g_x);
    cudaGetSymbolAddress((void**)&peb,  g_pe);
    cudaGetSymbolAddress((void**)&hb,   g_h);
    cudaGetSymbolAddress((void**)&qb,   g_q);
    cudaGetSymbolAddress((void**)&kvb,  g_kv);
    cudaGetSymbolAddress((void**)&ob,   g_o);
    cudaGetSymbolAddress((void**)&fb,   g_ffn);
    cudaGetSymbolAddress((void**)&wqh,  g_wq);
    cudaGetSymbolAddress((void**)&wkvh, g_wkv);
    cudaGetSymbolAddress((void**)&woh,  g_wo);
    cudaGetSymbolAddress((void**)&w1h,  g_w1);
    cudaGetSymbolAddress((void**)&w2h,  g_w2);

    // one-time weight conversions (all layers)
    cvt(Wq,  wqh,  (long long)LL*DD*DD);
    cvt(Wkv, wkvh, (long long)LL*DD*2*DD);
    cvt(Wo,  woh,  (long long)LL*DD*DD);
    cvt(W1,  w1h,  (long long)LL*DD*DI);
    cvt(W2,  w2h,  (long long)LL*DI*DD);

    pe_kernel<<<(SS*DD + 255)/256, 256>>>(peb);
    embed_kernel<<<(NTOK*DD)/256, 256>>>(tokens, emb, peb, xb);

    for (int l = 0; l < LL; l++){
        // ---- attention sublayer ----
        ln_kernel<<<NTOK, 256>>>(xb, ln_attn_g + l*DD, ln_attn_b + l*DD, nullptr, hb);

        big_gemm(hb, DD, wqh  + (long long)l*DD*DD,   DD,   nullptr, qb,  DD,
                 bq  + l*DD,   nullptr, NTOK, DD,   DD, 0);
        big_gemm(hb, DD, wkvh + (long long)l*DD*2*DD, 2*DD, nullptr, kvb, 2*DD,
                 bkv + l*2*DD, nullptr, NTOK, 2*DD, DD, 0);

        flash_kernel<<<dim3(SS/128, BB*HH), 256, FSM>>>(qb, kvb, ob, lengths);

        // x = x + o @ Wo + bo
        big_gemm(ob, DD, woh + (long long)l*DD*DD, DD, xb, nullptr, DD,
                 bo + l*DD, xb, NTOK, DD, DD, 0);

        // ---- FFN sublayer ----
        ln_kernel<<<NTOK, 256>>>(xb, ln_ffn_g + l*DD, ln_ffn_b + l*DD, nullptr, hb);
        big_gemm(hb, DD, w1h + (long long)l*DD*DI, DI, nullptr, fb, DI,
                 b1 + l*DI, nullptr, NTOK, DI, DD, 1);
        big_gemm(fb, DI, w2h + (long long)l*DI*DD, DD, xb, nullptr, DD,
                 b2 + l*DD, xb, NTOK, DD, DI, 0);
    }

    ln_kernel<<<NTOK, 256>>>(xb, ln_f_g, ln_f_b, out, nullptr);
}

// round 15
// speedup vs baseline: 3.5567x; 1.0592x over previous
#include <cuda_runtime.h>
#include <cuda_fp16.h>
#include <math.h>
#include <stdint.h>

#define BB 8
#define SS 512
#define DD 1024
#define HH 16
#define DI 4096
#define LL 6
#define NTOK (BB*SS)
#define EPSLN 1e-5f

// ---------------- device scratch ----------------
__device__ __align__(16) float  g_x   [NTOK*DD];
__device__ __align__(16) float  g_pe  [SS*DD];
__device__ __align__(16) float  g_bqkv[LL*3*DD];
__device__ __align__(16) __half g_h   [NTOK*DD];
__device__ __align__(16) __half g_qkv [NTOK*3*DD];
__device__ __align__(16) __half g_o   [NTOK*DD];
__device__ __align__(16) __half g_ffn [NTOK*DI];
__device__ __align__(16) __half g_wqkv[LL*DD*3*DD];
__device__ __align__(16) __half g_wo  [LL*DD*DD];
__device__ __align__(16) __half g_w1  [LL*DD*DI];
__device__ __align__(16) __half g_w2  [LL*DI*DD];

// ---------------- helpers ----------------
__device__ __forceinline__ float warpSum(float v){
#pragma unroll
    for (int o = 16; o; o >>= 1) v += __shfl_xor_sync(0xffffffffu, v, o);
    return v;
}
__device__ __forceinline__ uint32_t smem_u32(const void* p){
    uint32_t a;
    asm("{ .reg .u64 t; cvta.to.shared.u64 t, %1; cvt.u32.u64 %0, t; }" : "=r"(a) : "l"(p));
    return a;
}
__device__ __forceinline__ void cp16(uint32_t s, const void* g){
    asm volatile("cp.async.cg.shared.global [%0], [%1], 16;" :: "r"(s), "l"(g));
}
__device__ __forceinline__ void cp_commit(){
    asm volatile("cp.async.commit_group;" ::: "memory");
}
__device__ __forceinline__ void cp_wait1(){
    asm volatile("cp.async.wait_group 1;" ::: "memory");
}
__device__ __forceinline__ void cp_wait0(){
    asm volatile("cp.async.wait_group 0;" ::: "memory");
}
__device__ __forceinline__ void mma16(float* c, uint32_t a0, uint32_t a1, uint32_t a2, uint32_t a3,
                                      uint32_t b0, uint32_t b1){
    asm volatile("mma.sync.aligned.m16n8k16.row.col.f32.f16.f16.f32 "
        "{%0,%1,%2,%3}, {%4,%5,%6,%7}, {%8,%9}, {%0,%1,%2,%3};"
        : "+f"(c[0]), "+f"(c[1]), "+f"(c[2]), "+f"(c[3])
        : "r"(a0), "r"(a1), "r"(a2), "r"(a3), "r"(b0), "r"(b1));
}
__device__ __forceinline__ void ldsm4(uint32_t& r0, uint32_t& r1, uint32_t& r2, uint32_t& r3, uint32_t a){
    asm volatile("ldmatrix.sync.aligned.m8n8.x4.shared.b16 {%0,%1,%2,%3}, [%4];"
        : "=r"(r0), "=r"(r1), "=r"(r2), "=r"(r3) : "r"(a));
}
__device__ __forceinline__ void ldsm4t(uint32_t& r0, uint32_t& r1, uint32_t& r2, uint32_t& r3, uint32_t a){
    asm volatile("ldmatrix.sync.aligned.m8n8.x4.trans.shared.b16 {%0,%1,%2,%3}, [%4];"
        : "=r"(r0), "=r"(r1), "=r"(r2), "=r"(r3) : "r"(a));
}
__device__ __forceinline__ uint32_t packh2(float a, float b){
    __half2 h = __floats2half2_rn(a, b);
    return *(uint32_t*)&h;
}

// ---------------- weight prep kernels ----------------
__global__ void cvt_kernel(const float* __restrict__ src, __half* __restrict__ dst, int n4){
    int i = blockIdx.x * 256 + threadIdx.x;
    if (i >= n4) return;
    float4 v = ((const float4*)src)[i];
    __half2 h0 = __floats2half2_rn(v.x, v.y);
    __half2 h1 = __floats2half2_rn(v.z, v.w);
    uint2 o; o.x = *(uint32_t*)&h0; o.y = *(uint32_t*)&h1;
    ((uint2*)dst)[i] = o;
}

// merge Wq[l][k][1024] + Wkv[l][k][2048] -> wqkv[l][k][3072] (fp16), 4 elems/thread
__global__ void merge_qkv_kernel(const float* __restrict__ Wq, const float* __restrict__ Wkv,
                                 __half* __restrict__ dst){
    long long i4 = (long long)blockIdx.x * 256 + threadIdx.x;   // over LL*DD*3072/4
    if (i4 >= (long long)LL*DD*3*DD/4) return;
    long long idx = i4 * 4;
    int c = (int)(idx % (3*DD));
    long long lk = idx / (3*DD);
    int k = (int)(lk % DD);
    int l = (int)(lk / DD);
    const float* src = (c < DD)
        ? Wq  + ((long long)l*DD + k)*DD + c
        : Wkv + ((long long)l*DD + k)*2*DD + (c - DD);
    float4 v = *(const float4*)src;
    __half2 h0 = __floats2half2_rn(v.x, v.y);
    __half2 h1 = __floats2half2_rn(v.z, v.w);
    uint2 o; o.x = *(uint32_t*)&h0; o.y = *(uint32_t*)&h1;
    *(uint2*)(dst + idx) = o;
}

__global__ void merge_bias_kernel(const float* __restrict__ bq, const float* __restrict__ bkv,
                                  float* __restrict__ dst){
    int idx = blockIdx.x * 256 + threadIdx.x;
    if (idx >= LL*3*DD) return;
    int c = idx % (3*DD), l = idx / (3*DD);
    dst[idx] = (c < DD) ? bq[l*DD + c] : bkv[l*2*DD + (c - DD)];
}

// ---------------- positional encoding / embedding ----------------
__global__ void pe_kernel(float* __restrict__ pe){
    int idx = blockIdx.x * 256 + threadIdx.x;
    if (idx >= SS*DD) return;
    int s = idx / DD, d = idx % DD;
    double expo  = (double)(2 * (d / 2)) / (double)DD;
    double denom = pow(10000.0, expo);
    double ang   = (double)s / denom;
    pe[idx] = (float)((d % 2 == 0) ? sin(ang) : cos(ang));
}

__global__ void embed_kernel(const int* __restrict__ tokens,
                             const float* __restrict__ emb,
                             const float* __restrict__ pe,
                             float* __restrict__ x){
    int idx = blockIdx.x * 256 + threadIdx.x;
    int row = idx / DD, d = idx % DD;
    int s = row % SS;
    int t = tokens[row];
    x[idx] = emb[(long long)t * DD + d] * 32.0f + pe[s * DD + d];
}

// ---------------- layernorm: fp32 out (yf) or fp16 out (yh) ----------------
__global__ void ln_kernel(const float* __restrict__ x,
                          const float* __restrict__ g,
                          const float* __restrict__ be,
                          float* __restrict__ yf, __half* __restrict__ yh){
    int row = blockIdx.x, tid = threadIdx.x;
    const float4* xr = (const float4*)(x + (long long)row * DD);
    float4 v = xr[tid];
    float s  = v.x + v.y + v.z + v.w;
    float sq = v.x*v.x + v.y*v.y + v.z*v.z + v.w*v.w;
    __shared__ float sh[16];
    s  = warpSum(s);
    sq = warpSum(sq);
    int wid = tid >> 5, lid = tid & 31;
    if (lid == 0){ sh[wid] = s; sh[wid + 8] = sq; }
    __syncthreads();
    if (wid == 0){
        float a  = (lid < 8) ? sh[lid]     : 0.f;
        float b2 = (lid < 8) ? sh[lid + 8] : 0.f;
        a  = warpSum(a);
        b2 = warpSum(b2);
        if (lid == 0){ sh[0] = a; sh[1] = b2; }
    }
    __syncthreads();
    float mean = sh[0] * (1.0f / DD);
    float var  = sh[1] * (1.0f / DD) - mean * mean;
    float rstd = rsqrtf(var + EPSLN);
    float4 gv = ((const float4*)g)[tid];
    float4 bv = ((const float4*)be)[tid];
    float4 o;
    o.x = (v.x - mean) * rstd * gv.x + bv.x;
    o.y = (v.y - mean) * rstd * gv.y + bv.y;
    o.z = (v.z - mean) * rstd * gv.z + bv.z;
    o.w = (v.w - mean) * rstd * gv.w + bv.w;
    if (yh){
        __half2* hp = (__half2*)(yh + (long long)row * DD + 4 * tid);
        hp[0] = __floats2half2_rn(o.x, o.y);
        hp[1] = __floats2half2_rn(o.z, o.w);
    } else {
        ((float4*)(yf + (long long)row * DD))[tid] = o;
    }
}

// ---------------- fused flash attention (reads merged qkv [token][3072]) ----------
#define QRS 72
#define KRS 72
#define VRS 72
#define FSM ((128*QRS + 2*128*KRS + 2*128*VRS) * 2)

__global__ void __launch_bounds__(256, 1)
flash_kernel(const __half* __restrict__ qkv, __half* __restrict__ o,
             const int* __restrict__ lengths)
{
    extern __shared__ __half sm[];
    const uint32_t sQu = smem_u32(sm);
    const uint32_t sKu = sQu + 128*QRS*2;
    const uint32_t sVu = sKu + 2*128*KRS*2;

    const int tid = threadIdx.x, wid = tid >> 5, lid = tid & 31;
    const int tg = lid >> 2, tig = lid & 3;
    const int lid7 = lid & 7;
    const int z = blockIdx.y, b = z >> 4, h = z & 15;
    const int q0 = blockIdx.x * 128;
    const int len = lengths[b];
    const int jmax = (len + 127) >> 7;

    const __half* Qg = qkv + (long long)(b * 512 + q0) * 3072 + h * 64;
    const __half* Kg = qkv + (long long)b * 512 * 3072 + 1024 + h * 64;  // V at +1024 more

    // stage Q
#pragma unroll
    for (int i = 0; i < 4; i++){
        int c = tid + 256 * i;
        int row = c >> 3, col = (c & 7) * 8;
        cp16(sQu + (uint32_t)(row * QRS + col) * 2, Qg + (long long)row * 3072 + col);
    }
    cp_commit();

#define KVISSUE(j) do{ \
    int buf_ = (j) & 1; \
    uint32_t kb_ = sKu + (uint32_t)(buf_ * 128 * KRS) * 2; \
    uint32_t vb_ = sVu + (uint32_t)(buf_ * 128 * VRS) * 2; \
    const __half* Kj_ = Kg + (long long)(j) * 128 * 3072; \
    _Pragma("unroll") \
    for (int i = 0; i < 4; i++){ \
        int c = tid + 256 * i; \
        int row = c >> 3, col = (c & 7) * 8; \
        cp16(kb_ + (uint32_t)(row * KRS + col) * 2, Kj_ + (long long)row * 3072 + col); \
        cp16(vb_ + (uint32_t)(row * VRS + col) * 2, Kj_ + 1024 + (long long)row * 3072 + col); \
    } \
    cp_commit(); \
}while(0)

    KVISSUE(0);

    const uint32_t a_row = (uint32_t)(wid * 16 + ((lid >> 3) & 1) * 8 + lid7);
    const uint32_t a_k   = (uint32_t)((lid >> 4) * 8);
    const uint32_t b_rk  = (uint32_t)(((lid >> 4) & 1) * 8 + lid7);
    const uint32_t b_ko  = (uint32_t)(((lid >> 3) & 1) * 8);
    const uint32_t vt_row = (uint32_t)(lid & 15);
    const uint32_t vt_col = (uint32_t)((lid >> 4) * 8);

    float m0 = -1e30f, m1 = -1e30f, l0 = 0.f, l1 = 0.f;
    float oacc[8][4];
#pragma unroll
    for (int f = 0; f < 8; f++)
#pragma unroll
        for (int qd = 0; qd < 4; qd++) oacc[f][qd] = 0.f;

    uint32_t qf[4][4];

    for (int j = 0; j < jmax; j++){
        cp_wait0();
        __syncthreads();
        if (j + 1 < jmax) KVISSUE(j + 1);
        if (j == 0){
#pragma unroll
            for (int k16 = 0; k16 < 4; k16++)
                ldsm4(qf[k16][0], qf[k16][1], qf[k16][2], qf[k16][3],
                      sQu + (uint32_t)(a_row * QRS + a_k + k16 * 16) * 2);
        }
        const uint32_t kb = sKu + (uint32_t)((j & 1) * 128 * KRS) * 2;
        const uint32_t vb = sVu + (uint32_t)((j & 1) * 128 * VRS) * 2;

        float sacc[16][4];
#pragma unroll
        for (int ni = 0; ni < 16; ni++)
#pragma unroll
            for (int qd = 0; qd < 4; qd++) sacc[ni][qd] = 0.f;
#pragma unroll
        for (int k16 = 0; k16 < 4; k16++){
#pragma unroll
            for (int g = 0; g < 8; g++){
                uint32_t b0, b1, b2, b3;
                ldsm4(b0, b1, b2, b3,
                      kb + (uint32_t)((g * 16 + b_rk) * KRS + b_ko + k16 * 16) * 2);
                mma16(sacc[2*g    ], qf[k16][0], qf[k16][1], qf[k16][2], qf[k16][3], b0, b1);
                mma16(sacc[2*g + 1], qf[k16][0], qf[k16][1], qf[k16][2], qf[k16][3], b2, b3);
            }
        }

        const int lim = len - j * 128;
        float rm0 = -1e30f, rm1 = -1e30f;
#pragma unroll
        for (int ni = 0; ni < 16; ni++){
            int c0 = 8 * ni + 2 * tig;
            sacc[ni][0] *= 0.125f; sacc[ni][1] *= 0.125f;
            sacc[ni][2] *= 0.125f; sacc[ni][3] *= 0.125f;
            if (c0 >= lim)     { sacc[ni][0] = -1e30f; sacc[ni][2] = -1e30f; }
            if (c0 + 1 >= lim) { sacc[ni][1] = -1e30f; sacc[ni][3] = -1e30f; }
            rm0 = fmaxf(rm0, fmaxf(sacc[ni][0], sacc[ni][1]));
            rm1 = fmaxf(rm1, fmaxf(sacc[ni][2], sacc[ni][3]));
        }
        rm0 = fmaxf(rm0, __shfl_xor_sync(0xffffffffu, rm0, 1));
        rm0 = fmaxf(rm0, __shfl_xor_sync(0xffffffffu, rm0, 2));
        rm1 = fmaxf(rm1, __shfl_xor_sync(0xffffffffu, rm1, 1));
        rm1 = fmaxf(rm1, __shfl_xor_sync(0xffffffffu, rm1, 2));

        float mn0 = fmaxf(m0, rm0), mn1 = fmaxf(m1, rm1);
        float al0 = __expf(m0 - mn0), al1 = __expf(m1 - mn1);
        m0 = mn0; m1 = mn1;

        float rs0 = 0.f, rs1 = 0.f;
        uint32_t pa[16], pb[16];
#pragma unroll
        for (int ni = 0; ni < 16; ni++){
            float p0 = __expf(sacc[ni][0] - mn0);
            float p1 = __expf(sacc[ni][1] - mn0);
            float p2 = __expf(sacc[ni][2] - mn1);
            float p3 = __expf(sacc[ni][3] - mn1);
            rs0 += p0 + p1; rs1 += p2 + p3;
            pa[ni] = packh2(p0, p1);
            pb[ni] = packh2(p2, p3);
        }
        rs0 += __shfl_xor_sync(0xffffffffu, rs0, 1);
        rs0 += __shfl_xor_sync(0xffffffffu, rs0, 2);
        rs1 += __shfl_xor_sync(0xffffffffu, rs1, 1);
        rs1 += __shfl_xor_sync(0xffffffffu, rs1, 2);
        l0 = l0 * al0 + rs0;
        l1 = l1 * al1 + rs1;

#pragma unroll
        for (int f = 0; f < 8; f++){
            oacc[f][0] *= al0; oacc[f][1] *= al0;
            oacc[f][2] *= al1; oacc[f][3] *= al1;
        }
#pragma unroll
        for (int j2 = 0; j2 < 8; j2++){
#pragma unroll
            for (int gd = 0; gd < 4; gd++){
                uint32_t b0, b1, b2, b3;
                ldsm4t(b0, b1, b2, b3,
                       vb + (uint32_t)((j2 * 16 + vt_row) * VRS + gd * 16 + vt_col) * 2);
                mma16(oacc[2*gd    ], pa[2*j2], pb[2*j2], pa[2*j2+1], pb[2*j2+1], b0, b1);
                mma16(oacc[2*gd + 1], pa[2*j2], pb[2*j2], pa[2*j2+1], pb[2*j2+1], b2, b3);
            }
        }
    }
#undef KVISSUE

    float inv0 = 1.0f / l0, inv1 = 1.0f / l1;
    int r0 = q0 + wid * 16 + tg;
    long long t0 = (long long)(b * 512 + r0) * 1024 + h * 64;
    long long t1 = t0 + 8 * 1024;
#pragma unroll
    for (int f = 0; f < 8; f++){
        int col = 8 * f + 2 * tig;
        *(__half2*)(o + t0 + col) = __floats2half2_rn(oacc[f][0] * inv0, oacc[f][1] * inv0);
        *(__half2*)(o + t1 + col) = __floats2half2_rn(oacc[f][2] * inv1, oacc[f][3] * inv1);
    }
}

// ---------------- fp16 GEMM: A [M][K], B [K][N], BK=64, 3-stage ----------------
#define RSA 72
#define RSB 136
#define ASZ (128*RSA)
#define STGH (ASZ + 64*RSB)
#define SMH (3 * STGH * 2)

__global__ void __launch_bounds__(256, 2)
hgemm(int K,
      const __half* __restrict__ A, int lda,
      const __half* __restrict__ B, int ldb,
      float* __restrict__ Cf, __half* __restrict__ Ch, int ldc,
      const float* __restrict__ bias, const float* __restrict__ res,
      int relu)
{
    extern __shared__ __half smp[];

    const int tid = threadIdx.x;
    const int wid = tid >> 5, lid = tid & 31;
    const int wm = wid >> 1, wn = wid & 1;
    const int tg = lid >> 2, tig = lid & 3;
    const int lid7 = lid & 7;

    const int m0 = blockIdx.y * 128;
    const int n0 = blockIdx.x * 128;
    const int nst = K >> 6;

    const uint32_t smem0 = smem_u32(smp);

    const uint32_t a_base = (uint32_t)((wm * 32 + ((lid >> 3) & 1) * 8 + lid7) * RSA
                                       + (lid >> 4) * 8) * 2;
    const uint32_t bt_base = (uint32_t)(ASZ + (lid & 15) * RSB + wn * 64 + (lid >> 4) * 8) * 2;

    float acc[2][8][4];
#pragma unroll
    for (int i = 0; i < 2; i++)
#pragma unroll
        for (int j = 0; j < 8; j++)
#pragma unroll
            for (int qd = 0; qd < 4; qd++) acc[i][j][qd] = 0.f;

#define ISSUE(sidx) do{ \
    uint32_t sb = smem0 + (uint32_t)(((sidx) % 3) * STGH) * 2; \
    const int k0_ = (sidx) << 6; \
    _Pragma("unroll") \
    for (int i = 0; i < 4; i++){ \
        int c = tid + 256 * i; \
        int row = c >> 3, col = (c & 7) * 8; \
        cp16(sb + (uint32_t)(row * RSA + col) * 2, \
             A + (long long)(m0 + row) * lda + k0_ + col); \
    } \
    _Pragma("unroll") \
    for (int i = 0; i < 4; i++){ \
        int c = tid + 256 * i; \
        int row = c >> 4, col = (c & 15) * 8; \
        cp16(sb + (uint32_t)(ASZ + row * RSB + col) * 2, \
             B + (long long)(k0_ + row) * ldb + n0 + col); \
    } \
    cp_commit(); \
}while(0)

    ISSUE(0);
    if (nst > 1) ISSUE(1);

    for (int s = 0; s < nst; s++){
        if (s + 1 < nst) cp_wait1(); else cp_wait0();
        __syncthreads();
        if (s + 2 < nst) ISSUE(s + 2);

        const uint32_t stg = smem0 + (uint32_t)((s % 3) * STGH) * 2;
#pragma unroll
        for (int k16 = 0; k16 < 4; k16++){
            uint32_t af[2][4];
#pragma unroll
            for (int mi = 0; mi < 2; mi++)
                ldsm4(af[mi][0], af[mi][1], af[mi][2], af[mi][3],
                      stg + a_base + (uint32_t)(mi * 16 * RSA + k16 * 16) * 2);
#pragma unroll
            for (int nip = 0; nip < 4; nip++){
                uint32_t b0, b1, b2, b3;
                ldsm4t(b0, b1, b2, b3,
                       stg + bt_base + (uint32_t)(k16 * 16 * RSB + nip * 16) * 2);
#pragma unroll
                for (int mi = 0; mi < 2; mi++){
                    mma16(acc[mi][2*nip    ], af[mi][0], af[mi][1], af[mi][2], af[mi][3], b0, b1);
                    mma16(acc[mi][2*nip + 1], af[mi][0], af[mi][1], af[mi][2], af[mi][3], b2, b3);
                }
            }
        }
    }
#undef ISSUE

    // ---- epilogue ----
#pragma unroll
    for (int mi = 0; mi < 2; mi++){
        int r0 = m0 + wm * 32 + mi * 16 + tg;
#pragma unroll
        for (int ni = 0; ni < 8; ni++){
            int cc = n0 + wn * 64 + ni * 8 + tig * 2;
            float bx = 0.f, by = 0.f;
            if (bias){ bx = bias[cc]; by = bias[cc + 1]; }
#pragma unroll
            for (int hrow = 0; hrow < 2; hrow++){
                int r = r0 + hrow * 8;
                float v0 = acc[mi][ni][hrow * 2 + 0] + bx;
                float v1 = acc[mi][ni][hrow * 2 + 1] + by;
                if (relu){ v0 = fmaxf(v0, 0.f); v1 = fmaxf(v1, 0.f); }
                long long g = (long long)r * ldc + cc;
                if (res){
                    float2 rv = *(const float2*)(res + g);
                    v0 += rv.x; v1 += rv.y;
                }
                if (Ch){
                    *(__half2*)(Ch + g) = __floats2half2_rn(v0, v1);
                } else {
                    float2 o; o.x = v0; o.y = v1;
                    *(float2*)(Cf + g) = o;
                }
            }
        }
    }
}

// ---------------- host side ----------------
static void big_gemm(const __half* A, int lda, const __half* B, int ldb,
                     float* Cf, __half* Ch, int ldc,
                     const float* bias, const float* res,
                     int M, int N, int K, int relu){
    dim3 grid(N / 128, M / 128, 1);
    hgemm<<<grid, 256, SMH>>>(K, A, lda, B, ldb, Cf, Ch, ldc, bias, res, relu);
}

static void cvt(const float* src, __half* dst, long long n){
    int n4 = (int)(n / 4);
    cvt_kernel<<<(n4 + 255) / 256, 256>>>(src, dst, n4);
}

extern "C" void kernel_launch(void* const* d_in, const int* in_sizes, int n_in,
                              void* d_out, int out_size){
    const int*   tokens    = (const int*)  d_in[0];
    const int*   lengths   = (const int*)  d_in[1];
    const float* emb       = (const float*)d_in[2];
    const float* Wq        = (const float*)d_in[3];
    const float* bq        = (const float*)d_in[4];
    const float* Wkv       = (const float*)d_in[5];
    const float* bkv       = (const float*)d_in[6];
    const float* Wo        = (const float*)d_in[7];
    const float* bo        = (const float*)d_in[8];
    const float* ln_attn_g = (const float*)d_in[9];
    const float* ln_attn_b = (const float*)d_in[10];
    const float* W1        = (const float*)d_in[11];
    const float* b1        = (const float*)d_in[12];
    const float* W2        = (const float*)d_in[13];
    const float* b2        = (const float*)d_in[14];
    const float* ln_ffn_g  = (const float*)d_in[15];
    const float* ln_ffn_b  = (const float*)d_in[16];
    const float* ln_f_g    = (const float*)d_in[17];
    const float* ln_f_b    = (const float*)d_in[18];
    float* out = (float*)d_out;

    cudaFuncSetAttribute((const void*)hgemm, cudaFuncAttributeMaxDynamicSharedMemorySize, SMH);
    cudaFuncSetAttribute((const void*)flash_kernel, cudaFuncAttributeMaxDynamicSharedMemorySize, FSM);

    float *xb, *peb, *bqkvb;
    __half *hb, *qkvb, *ob, *fb;
    __half *wqkvh, *woh, *w1h, *w2h;
    cudaGetSymbolAddress((void**)&xb,    g_x);
    cudaGetSymbolAddress((void**)&peb,   g_pe);
    cudaGetSymbolAddress((void**)&bqkvb, g_bqkv);
    cudaGetSymbolAddress((void**)&hb,    g_h);
    cudaGetSymbolAddress((void**)&qkvb,  g_qkv);
    cudaGetSymbolAddress((void**)&ob,    g_o);
    cudaGetSymbolAddress((void**)&fb,    g_ffn);
    cudaGetSymbolAddress((void**)&wqkvh, g_wqkv);
    cudaGetSymbolAddress((void**)&woh,   g_wo);
    cudaGetSymbolAddress((void**)&w1h,   g_w1);
    cudaGetSymbolAddress((void**)&w2h,   g_w2);

    // one-time weight prep
    {
        long long n4 = (long long)LL*DD*3*DD/4;
        merge_qkv_kernel<<<(unsigned)((n4 + 255) / 256), 256>>>(Wq, Wkv, wqkvh);
        merge_bias_kernel<<<(LL*3*DD + 255)/256, 256>>>(bq, bkv, bqkvb);
    }
    cvt(Wo, woh, (long long)LL*DD*DD);
    cvt(W1, w1h, (long long)LL*DD*DI);
    cvt(W2, w2h, (long long)LL*DI*DD);

    pe_kernel<<<(SS*DD + 255)/256, 256>>>(peb);
    embed_kernel<<<(NTOK*DD)/256, 256>>>(tokens, emb, peb, xb);

    for (int l = 0; l < LL; l++){
        // ---- attention sublayer ----
        ln_kernel<<<NTOK, 256>>>(xb, ln_attn_g + l*DD, ln_attn_b + l*DD, nullptr, hb);

        big_gemm(hb, DD, wqkvh + (long long)l*DD*3*DD, 3*DD, nullptr, qkvb, 3*DD,
                 bqkvb + l*3*DD, nullptr, NTOK, 3*DD, DD, 0);

        flash_kernel<<<dim3(SS/128, BB*HH), 256, FSM>>>(qkvb, ob, lengths);

        big_gemm(ob, DD, woh + (long long)l*DD*DD, DD, xb, nullptr, DD,
                 bo + l*DD, xb, NTOK, DD, DD, 0);

        // ---- FFN sublayer ----
        ln_kernel<<<NTOK, 256>>>(xb, ln_ffn_g + l*DD, ln_ffn_b + l*DD, nullptr, hb);
        big_gemm(hb, DD, w1h + (long long)l*DD*DI, DI, nullptr, fb, DI,
                 b1 + l*DI, nullptr, NTOK, DI, DD, 1);
        big_gemm(fb, DI, w2h + (long long)l*DI*DD, DD, xb, nullptr, DD,
                 b2 + l*DD, xb, NTOK, DD, DI, 0);
    }

    ln_kernel<<<NTOK, 256>>>(xb, ln_f_g, ln_f_b, out, nullptr);
}